// round 1
// baseline (speedup 1.0000x reference)
#include <cuda_runtime.h>
#include <math.h>

// Problem constants
#define BB 2
#define SS 2048
#define DD 1024
#define HH 16
#define DH 64
#define MM (BB * SS)   // 4096

// Scratch (device globals; allocation APIs are forbidden)
__device__ float g_q[BB * HH * SS * DH];     // (B,H,S,DH), pre-scaled by 1/sqrt(DH)
__device__ float g_k[BB * HH * SS * DH];
__device__ float g_v[BB * HH * SS * DH];
__device__ float g_attn[BB * SS * DD];       // merged heads (B,S,D)

// ---------------------------------------------------------------------------
// NT GEMM: C[m,n] = sum_k A[m,k] * W[n,k] + bias[n], optionally scaled.
// A: M x 1024 row-major, W: N x 1024 row-major. M=4096, N=1024.
// MODE 0: write to (B,H,S,DH) permuted layout (QKV projections)
// MODE 1: write to (M,N) row-major (output projection)
// Tiles: 64x64x16, 256 threads, 4x4 per-thread microtile.
// ---------------------------------------------------------------------------
#define GBM 64
#define GBN 64
#define GBK 16

template <int MODE>
__global__ __launch_bounds__(256)
void gemm_nt(const float* __restrict__ A, const float* __restrict__ W,
             const float* __restrict__ bias, float* __restrict__ C, float scale) {
    __shared__ float As[GBK][GBM];
    __shared__ float Bs[GBK][GBN];

    const int tid = threadIdx.x;
    const int tx = tid & 15;        // 0..15 -> n microtile
    const int ty = tid >> 4;        // 0..15 -> m microtile
    const int m0 = blockIdx.x * GBM;
    const int n0 = blockIdx.y * GBN;

    const int lrow = tid >> 2;      // 0..63
    const int lkv  = tid & 3;       // 0..3  (float4 within BK=16)

    const float* Ap = A + (size_t)(m0 + lrow) * DD + lkv * 4;
    const float* Wp = W + (size_t)(n0 + lrow) * DD + lkv * 4;

    float acc[4][4] = {};

    for (int k0 = 0; k0 < DD; k0 += GBK) {
        float4 av = *(const float4*)(Ap + k0);
        float4 wv = *(const float4*)(Wp + k0);
        As[lkv * 4 + 0][lrow] = av.x;
        As[lkv * 4 + 1][lrow] = av.y;
        As[lkv * 4 + 2][lrow] = av.z;
        As[lkv * 4 + 3][lrow] = av.w;
        Bs[lkv * 4 + 0][lrow] = wv.x;
        Bs[lkv * 4 + 1][lrow] = wv.y;
        Bs[lkv * 4 + 2][lrow] = wv.z;
        Bs[lkv * 4 + 3][lrow] = wv.w;
        __syncthreads();

#pragma unroll
        for (int kk = 0; kk < GBK; ++kk) {
            float4 a = *(const float4*)&As[kk][ty * 4];
            float4 b = *(const float4*)&Bs[kk][tx * 4];
            acc[0][0] = fmaf(a.x, b.x, acc[0][0]);
            acc[0][1] = fmaf(a.x, b.y, acc[0][1]);
            acc[0][2] = fmaf(a.x, b.z, acc[0][2]);
            acc[0][3] = fmaf(a.x, b.w, acc[0][3]);
            acc[1][0] = fmaf(a.y, b.x, acc[1][0]);
            acc[1][1] = fmaf(a.y, b.y, acc[1][1]);
            acc[1][2] = fmaf(a.y, b.z, acc[1][2]);
            acc[1][3] = fmaf(a.y, b.w, acc[1][3]);
            acc[2][0] = fmaf(a.z, b.x, acc[2][0]);
            acc[2][1] = fmaf(a.z, b.y, acc[2][1]);
            acc[2][2] = fmaf(a.z, b.z, acc[2][2]);
            acc[2][3] = fmaf(a.z, b.w, acc[2][3]);
            acc[3][0] = fmaf(a.w, b.x, acc[3][0]);
            acc[3][1] = fmaf(a.w, b.y, acc[3][1]);
            acc[3][2] = fmaf(a.w, b.z, acc[3][2]);
            acc[3][3] = fmaf(a.w, b.w, acc[3][3]);
        }
        __syncthreads();
    }

    const int nb = n0 + tx * 4;
    float4 b4 = *(const float4*)&bias[nb];
#pragma unroll
    for (int i = 0; i < 4; ++i) {
        const int m = m0 + ty * 4 + i;
        float4 r;
        r.x = (acc[i][0] + b4.x) * scale;
        r.y = (acc[i][1] + b4.y) * scale;
        r.z = (acc[i][2] + b4.z) * scale;
        r.w = (acc[i][3] + b4.w) * scale;
        if (MODE == 0) {
            const int bb = m >> 11;          // m / S
            const int s  = m & (SS - 1);
            const int h  = nb >> 6;          // n / DH
            const int dh = nb & (DH - 1);
            *(float4*)(C + ((size_t)(bb * HH + h) * SS + s) * DH + dh) = r;
        } else {
            *(float4*)(C + (size_t)m * DD + nb) = r;
        }
    }
}

// ---------------------------------------------------------------------------
// Causal flash attention, fp32. One thread = one query row.
// Block: 128 threads = 128 queries. Key tiles of 64 staged in smem.
// Scores staged in smem -> one softmax rescale per tile.
// Q pre-scaled by 1/sqrt(DH) in the projection epilogue.
// ---------------------------------------------------------------------------
#define QB 128
#define TK 64
#define ATTN_SMEM ((TK * DH + TK * DH + TK * QB) * 4)   // 64 KB

__global__ __launch_bounds__(QB)
void attn_kernel(const float* __restrict__ q_g, const float* __restrict__ k_g,
                 const float* __restrict__ v_g, float* __restrict__ out_g) {
    extern __shared__ float sm[];
    float* Ks = sm;                    // TK x DH
    float* Vs = sm + TK * DH;          // TK x DH
    float* Sc = sm + 2 * TK * DH;      // TK x QB

    const int tid = threadIdx.x;
    const int qt = blockIdx.x;
    const int h  = blockIdx.y;
    const int bb = blockIdx.z;

    const size_t head_base = (size_t)(bb * HH + h) * SS * DH;
    const float4* qsrc = (const float4*)(q_g + head_base + (size_t)qt * QB * DH);
    const float4* kbase = (const float4*)(k_g + head_base);
    const float4* vbase = (const float4*)(v_g + head_base);

    float4 q[16];
#pragma unroll
    for (int i = 0; i < 16; ++i) q[i] = qsrc[tid * 16 + i];

    float4 acc[16];
#pragma unroll
    for (int i = 0; i < 16; ++i) acc[i] = make_float4(0.f, 0.f, 0.f, 0.f);

    float mrun = -1e30f;
    float lrun = 0.f;
    const int gq = qt * QB + tid;
    const int nkt = qt * 2 + 2;    // 64-key tiles covering [0, qt*128+128)

    for (int kt = 0; kt < nkt; ++kt) {
        const int kb = kt * TK;
        // Cooperative tile load: both tiles are contiguous 4 KB*4 blocks.
        const float4* ksrc = kbase + (size_t)kb * (DH / 4);
        const float4* vsrc = vbase + (size_t)kb * (DH / 4);
#pragma unroll
        for (int i = 0; i < 8; ++i) {
            ((float4*)Ks)[i * QB + tid] = ksrc[i * QB + tid];
            ((float4*)Vs)[i * QB + tid] = vsrc[i * QB + tid];
        }
        __syncthreads();

        const int klim = min(TK, gq - kb + 1);
        if (klim > 0) {
            const float4* Ks4 = (const float4*)Ks;
            float tmax = -1e30f;
            for (int kk = 0; kk < klim; ++kk) {
                const float4* kr = Ks4 + kk * 16;
                float s0 = 0.f, s1 = 0.f, s2 = 0.f, s3 = 0.f;
#pragma unroll
                for (int i = 0; i < 16; i += 4) {
                    float4 k0v = kr[i + 0];
                    float4 k1v = kr[i + 1];
                    float4 k2v = kr[i + 2];
                    float4 k3v = kr[i + 3];
                    s0 += q[i + 0].x * k0v.x + q[i + 0].y * k0v.y + q[i + 0].z * k0v.z + q[i + 0].w * k0v.w;
                    s1 += q[i + 1].x * k1v.x + q[i + 1].y * k1v.y + q[i + 1].z * k1v.z + q[i + 1].w * k1v.w;
                    s2 += q[i + 2].x * k2v.x + q[i + 2].y * k2v.y + q[i + 2].z * k2v.z + q[i + 2].w * k2v.w;
                    s3 += q[i + 3].x * k3v.x + q[i + 3].y * k3v.y + q[i + 3].z * k3v.z + q[i + 3].w * k3v.w;
                }
                const float s = (s0 + s1) + (s2 + s3);
                Sc[kk * QB + tid] = s;
                tmax = fmaxf(tmax, s);
            }

            const float mnew = fmaxf(mrun, tmax);
            const float corr = __expf(mrun - mnew);
            lrun *= corr;
#pragma unroll
            for (int i = 0; i < 16; ++i) {
                acc[i].x *= corr; acc[i].y *= corr; acc[i].z *= corr; acc[i].w *= corr;
            }
            const float4* Vs4 = (const float4*)Vs;
            for (int kk = 0; kk < klim; ++kk) {
                const float p = __expf(Sc[kk * QB + tid] - mnew);
                lrun += p;
                const float4* vr = Vs4 + kk * 16;
#pragma unroll
                for (int i = 0; i < 16; ++i) {
                    acc[i].x = fmaf(p, vr[i].x, acc[i].x);
                    acc[i].y = fmaf(p, vr[i].y, acc[i].y);
                    acc[i].z = fmaf(p, vr[i].z, acc[i].z);
                    acc[i].w = fmaf(p, vr[i].w, acc[i].w);
                }
            }
            mrun = mnew;
        }
        __syncthreads();
    }

    const float inv = 1.f / lrun;
    float4* obase = (float4*)(out_g + ((size_t)bb * SS + gq) * DD + h * DH);
#pragma unroll
    for (int i = 0; i < 16; ++i) {
        float4 r;
        r.x = acc[i].x * inv; r.y = acc[i].y * inv;
        r.z = acc[i].z * inv; r.w = acc[i].w * inv;
        obase[i] = r;
    }
}

// ---------------------------------------------------------------------------
extern "C" void kernel_launch(void* const* d_in, const int* in_sizes, int n_in,
                              void* d_out, int out_size) {
    const float* queries = (const float*)d_in[0];
    const float* keys    = (const float*)d_in[1];
    const float* values  = (const float*)d_in[2];
    const float* W_Q = (const float*)d_in[3];
    const float* b_Q = (const float*)d_in[4];
    const float* W_K = (const float*)d_in[5];
    const float* b_K = (const float*)d_in[6];
    const float* W_V = (const float*)d_in[7];
    const float* b_V = (const float*)d_in[8];
    const float* W_O = (const float*)d_in[9];
    const float* b_O = (const float*)d_in[10];
    float* out = (float*)d_out;

    float *q_p, *k_p, *v_p, *attn_p;
    cudaGetSymbolAddress((void**)&q_p, g_q);
    cudaGetSymbolAddress((void**)&k_p, g_k);
    cudaGetSymbolAddress((void**)&v_p, g_v);
    cudaGetSymbolAddress((void**)&attn_p, g_attn);

    static bool attr_set = false;
    if (!attr_set) {
        cudaFuncSetAttribute(attn_kernel, cudaFuncAttributeMaxDynamicSharedMemorySize, ATTN_SMEM);
        attr_set = true;
    }

    const float qscale = 1.0f / 8.0f;   // 1/sqrt(64)

    dim3 ggrid(MM / GBM, DD / GBN);     // 64 x 16
    gemm_nt<0><<<ggrid, 256>>>(queries, W_Q, b_Q, q_p, qscale);
    gemm_nt<0><<<ggrid, 256>>>(keys,    W_K, b_K, k_p, 1.0f);
    gemm_nt<0><<<ggrid, 256>>>(values,  W_V, b_V, v_p, 1.0f);

    dim3 agrid(SS / QB, HH, BB);        // 16 x 16 x 2
    attn_kernel<<<agrid, QB, ATTN_SMEM>>>(q_p, k_p, v_p, attn_p);

    gemm_nt<1><<<ggrid, 256>>>(attn_p, W_O, b_O, out, 1.0f);
}

// round 3
// speedup vs baseline: 1.5755x; 1.5755x over previous
#include <cuda_runtime.h>
#include <cuda_bf16.h>
#include <math.h>
#include <stdint.h>

// Problem constants
#define BB 2
#define SS 2048
#define DD 1024
#define HH 16
#define DH 64
#define MM (BB * SS)   // 4096

// ---------------------------------------------------------------------------
// Scratch (device globals; allocation APIs are forbidden)
// ---------------------------------------------------------------------------
__device__ float g_q[MM * DD];      // (B,H,S,DH), pre-scaled by 1/sqrt(DH)
__device__ float g_k[MM * DD];
__device__ float g_v[MM * DD];

// split-bf16 operands (hi + lo)
__device__ __nv_bfloat16 g_aq_h[MM * DD], g_aq_l[MM * DD];
__device__ __nv_bfloat16 g_ak_h[MM * DD], g_ak_l[MM * DD];
__device__ __nv_bfloat16 g_av_h[MM * DD], g_av_l[MM * DD];
__device__ __nv_bfloat16 g_at_h[MM * DD], g_at_l[MM * DD];
__device__ __nv_bfloat16 g_wq_h[DD * DD], g_wq_l[DD * DD];
__device__ __nv_bfloat16 g_wk_h[DD * DD], g_wk_l[DD * DD];
__device__ __nv_bfloat16 g_wv_h[DD * DD], g_wv_l[DD * DD];
__device__ __nv_bfloat16 g_wo_h[DD * DD], g_wo_l[DD * DD];

// ---------------------------------------------------------------------------
// PTX helpers (non-'a'-gated instructions only: mma.sync / ldmatrix / cp.async)
// ---------------------------------------------------------------------------
__device__ __forceinline__ uint32_t smem_u32(const void* p) {
    uint32_t a;
    asm("{ .reg .u64 t; cvta.to.shared.u64 t, %1; cvt.u32.u64 %0, t; }"
        : "=r"(a) : "l"(p));
    return a;
}

__device__ __forceinline__ void cpa16(uint32_t s, const void* g) {
    asm volatile("cp.async.cg.shared.global [%0], [%1], 16;"
                 :: "r"(s), "l"(g) : "memory");
}

__device__ __forceinline__ void ldsm4(uint32_t* r, uint32_t a) {
    asm volatile("ldmatrix.sync.aligned.m8n8.x4.shared.b16 {%0,%1,%2,%3}, [%4];"
                 : "=r"(r[0]), "=r"(r[1]), "=r"(r[2]), "=r"(r[3]) : "r"(a));
}

__device__ __forceinline__ void mma16816(float* d, const uint32_t* a,
                                         uint32_t b0, uint32_t b1) {
    asm volatile(
        "mma.sync.aligned.m16n8k16.row.col.f32.bf16.bf16.f32 "
        "{%0,%1,%2,%3}, {%4,%5,%6,%7}, {%8,%9}, {%0,%1,%2,%3};"
        : "+f"(d[0]), "+f"(d[1]), "+f"(d[2]), "+f"(d[3])
        : "r"(a[0]), "r"(a[1]), "r"(a[2]), "r"(a[3]), "r"(b0), "r"(b1));
}

// ---------------------------------------------------------------------------
// fp32 -> (hi, lo) bf16 split. hi = rn(x); lo = rn(x - hi).
// ---------------------------------------------------------------------------
__global__ __launch_bounds__(256)
void cvt_split(const float* __restrict__ x, __nv_bfloat16* __restrict__ hi,
               __nv_bfloat16* __restrict__ lo, int n4) {
    int i = blockIdx.x * 256 + threadIdx.x;
    if (i >= n4) return;
    float4 v = ((const float4*)x)[i];
    ushort4 h, l;
    {
        __nv_bfloat16 hb = __float2bfloat16(v.x);
        h.x = __bfloat16_as_ushort(hb);
        l.x = __bfloat16_as_ushort(__float2bfloat16(v.x - __bfloat162float(hb)));
    }
    {
        __nv_bfloat16 hb = __float2bfloat16(v.y);
        h.y = __bfloat16_as_ushort(hb);
        l.y = __bfloat16_as_ushort(__float2bfloat16(v.y - __bfloat162float(hb)));
    }
    {
        __nv_bfloat16 hb = __float2bfloat16(v.z);
        h.z = __bfloat16_as_ushort(hb);
        l.z = __bfloat16_as_ushort(__float2bfloat16(v.z - __bfloat162float(hb)));
    }
    {
        __nv_bfloat16 hb = __float2bfloat16(v.w);
        h.w = __bfloat16_as_ushort(hb);
        l.w = __bfloat16_as_ushort(__float2bfloat16(v.w - __bfloat162float(hb)));
    }
    ((ushort4*)hi)[i] = h;
    ((ushort4*)lo)[i] = l;
}

// ---------------------------------------------------------------------------
// Split-bf16 NT GEMM via mma.sync: C[m,n] = sum_k A[m,k] * W[n,k] (+bias)*scale
// D(fp32) += Ah*Bh + Ah*Bl + Al*Bh
// Tile 128x128x32, 256 threads (8 warps 4x2), warp tile 32x64.
// cp.async 2-stage pipeline. XOR-swizzled smem, conflict-free ldmatrix.
// MODE 0: store (B,H,S,DH) permuted; MODE 1: store (M,N) row-major.
// ---------------------------------------------------------------------------
#define BKT 32
#define STG_BYTES 32768
#define OFF_AH 0
#define OFF_AL 8192
#define OFF_BH 16384
#define OFF_BL 24576
#define GSM_TOTAL 65536

template <int MODE>
__global__ __launch_bounds__(256)
void gemm_mma(const __nv_bfloat16* __restrict__ Ah, const __nv_bfloat16* __restrict__ Al,
              const __nv_bfloat16* __restrict__ Bh, const __nv_bfloat16* __restrict__ Bl,
              const float* __restrict__ bias, float* __restrict__ C, float scale) {
    extern __shared__ char smc[];
    const uint32_t sb = smem_u32(smc);
    const int tid = threadIdx.x;
    const int lane = tid & 31, wid = tid >> 5;
    const int wm = (wid & 3) * 32;      // warp m offset in tile
    const int wn = (wid >> 2) * 64;     // warp n offset in tile
    const int m0 = blockIdx.x * 128, n0 = blockIdx.y * 128;

    const int lr = tid >> 2;            // loader row 0..63
    const int lc = tid & 3;             // loader 16B chunk 0..3

    float d[2][8][4] = {};

    // Stage loader: 128 rows x 32 bf16 per tile; 512 16B chunks; 2 per thread.
#define ISSUE_STAGE(it, sbase)                                                   \
    {                                                                            \
        const int k0 = (it) * BKT;                                               \
        _Pragma("unroll")                                                        \
        for (int rep = 0; rep < 2; ++rep) {                                      \
            const int row = lr + rep * 64;                                       \
            const uint32_t soff = row * 64 + ((lc ^ ((row >> 1) & 3)) << 4);     \
            const size_t ga = (size_t)(m0 + row) * DD + k0 + lc * 8;             \
            const size_t gb = (size_t)(n0 + row) * DD + k0 + lc * 8;             \
            cpa16(sb + (sbase) + OFF_AH + soff, Ah + ga);                        \
            cpa16(sb + (sbase) + OFF_AL + soff, Al + ga);                        \
            cpa16(sb + (sbase) + OFF_BH + soff, Bh + gb);                        \
            cpa16(sb + (sbase) + OFF_BL + soff, Bl + gb);                        \
        }                                                                        \
    }

    ISSUE_STAGE(0, 0);
    asm volatile("cp.async.commit_group;" ::: "memory");
    ISSUE_STAGE(1, STG_BYTES);
    asm volatile("cp.async.commit_group;" ::: "memory");

    for (int it = 0; it < DD / BKT; ++it) {
        asm volatile("cp.async.wait_group 1;" ::: "memory");
        __syncthreads();
        const uint32_t st = sb + (it & 1) * STG_BYTES;

#pragma unroll
        for (int ks = 0; ks < 2; ++ks) {
            uint32_t ah[2][4], al[2][4], bh[4][4], bl[4][4];
#pragma unroll
            for (int mi = 0; mi < 2; ++mi) {
                const int row = wm + mi * 16 + (lane & 15);
                const int ch = ks * 2 + (lane >> 4);
                const uint32_t ad = st + row * 64 + ((ch ^ ((row >> 1) & 3)) << 4);
                ldsm4(ah[mi], ad + OFF_AH);
                ldsm4(al[mi], ad + OFF_AL);
            }
#pragma unroll
            for (int ng = 0; ng < 4; ++ng) {
                const int row = wn + ng * 16 + (lane & 7) + ((lane >> 4) << 3);
                const int ch = ks * 2 + ((lane >> 3) & 1);
                const uint32_t bd = st + row * 64 + ((ch ^ ((row >> 1) & 3)) << 4);
                ldsm4(bh[ng], bd + OFF_BH);
                ldsm4(bl[ng], bd + OFF_BL);
            }
#pragma unroll
            for (int mi = 0; mi < 2; ++mi) {
#pragma unroll
                for (int n8 = 0; n8 < 8; ++n8) {
                    const int ng = n8 >> 1, hf = n8 & 1;
                    float* dd = d[mi][n8];
                    mma16816(dd, ah[mi], bh[ng][hf * 2], bh[ng][hf * 2 + 1]);
                    mma16816(dd, ah[mi], bl[ng][hf * 2], bl[ng][hf * 2 + 1]);
                    mma16816(dd, al[mi], bh[ng][hf * 2], bh[ng][hf * 2 + 1]);
                }
            }
        }
        __syncthreads();
        if (it + 2 < DD / BKT) {
            ISSUE_STAGE(it + 2, (it & 1) * STG_BYTES);
        }
        asm volatile("cp.async.commit_group;" ::: "memory");
    }
#undef ISSUE_STAGE

    // Epilogue. D fragment: lane holds rows {l/4, l/4+8}, cols {2(l%4), +1}.
    const int row = lane >> 2, colp = (lane & 3) * 2;
#pragma unroll
    for (int mi = 0; mi < 2; ++mi) {
#pragma unroll
        for (int n8 = 0; n8 < 8; ++n8) {
            const float* dd = d[mi][n8];
            const int n = n0 + wn + n8 * 8 + colp;
            const float2 b2 = *(const float2*)(bias + n);
#pragma unroll
            for (int rh = 0; rh < 2; ++rh) {
                const int m = m0 + wm + mi * 16 + row + rh * 8;
                float2 r;
                r.x = (dd[rh * 2 + 0] + b2.x) * scale;
                r.y = (dd[rh * 2 + 1] + b2.y) * scale;
                if (MODE == 0) {
                    const int bb = m >> 11, s = m & (SS - 1);
                    const int h = n >> 6, dh = n & (DH - 1);
                    *(float2*)(C + (((size_t)(bb * HH + h) * SS + s) * DH + dh)) = r;
                } else {
                    *(float2*)(C + (size_t)m * DD + n) = r;
                }
            }
        }
    }
}

// ---------------------------------------------------------------------------
// Causal flash attention, fp32. Epilogue writes split-bf16 (hi/lo) directly.
// ---------------------------------------------------------------------------
#define QB 128
#define TK 64
#define ATTN_SMEM ((TK * DH + TK * DH + TK * QB) * 4)   // 64 KB

__global__ __launch_bounds__(QB)
void attn_kernel(const float* __restrict__ q_g, const float* __restrict__ k_g,
                 const float* __restrict__ v_g,
                 __nv_bfloat16* __restrict__ oh, __nv_bfloat16* __restrict__ ol) {
    extern __shared__ float sm[];
    float* Ks = sm;
    float* Vs = sm + TK * DH;
    float* Sc = sm + 2 * TK * DH;

    const int tid = threadIdx.x;
    const int qt = blockIdx.x;
    const int h  = blockIdx.y;
    const int bb = blockIdx.z;

    const size_t head_base = (size_t)(bb * HH + h) * SS * DH;
    const float4* qsrc = (const float4*)(q_g + head_base + (size_t)qt * QB * DH);
    const float4* kbase = (const float4*)(k_g + head_base);
    const float4* vbase = (const float4*)(v_g + head_base);

    float4 q[16];
#pragma unroll
    for (int i = 0; i < 16; ++i) q[i] = qsrc[tid * 16 + i];

    float4 acc[16];
#pragma unroll
    for (int i = 0; i < 16; ++i) acc[i] = make_float4(0.f, 0.f, 0.f, 0.f);

    float mrun = -1e30f;
    float lrun = 0.f;
    const int gq = qt * QB + tid;
    const int nkt = qt * 2 + 2;

    for (int kt = 0; kt < nkt; ++kt) {
        const int kb = kt * TK;
        const float4* ksrc = kbase + (size_t)kb * (DH / 4);
        const float4* vsrc = vbase + (size_t)kb * (DH / 4);
#pragma unroll
        for (int i = 0; i < 8; ++i) {
            ((float4*)Ks)[i * QB + tid] = ksrc[i * QB + tid];
            ((float4*)Vs)[i * QB + tid] = vsrc[i * QB + tid];
        }
        __syncthreads();

        const int klim = min(TK, gq - kb + 1);
        if (klim > 0) {
            const float4* Ks4 = (const float4*)Ks;
            float tmax = -1e30f;
            for (int kk = 0; kk < klim; ++kk) {
                const float4* kr = Ks4 + kk * 16;
                float s0 = 0.f, s1 = 0.f, s2 = 0.f, s3 = 0.f;
#pragma unroll
                for (int i = 0; i < 16; i += 4) {
                    float4 k0v = kr[i + 0];
                    float4 k1v = kr[i + 1];
                    float4 k2v = kr[i + 2];
                    float4 k3v = kr[i + 3];
                    s0 += q[i + 0].x * k0v.x + q[i + 0].y * k0v.y + q[i + 0].z * k0v.z + q[i + 0].w * k0v.w;
                    s1 += q[i + 1].x * k1v.x + q[i + 1].y * k1v.y + q[i + 1].z * k1v.z + q[i + 1].w * k1v.w;
                    s2 += q[i + 2].x * k2v.x + q[i + 2].y * k2v.y + q[i + 2].z * k2v.z + q[i + 2].w * k2v.w;
                    s3 += q[i + 3].x * k3v.x + q[i + 3].y * k3v.y + q[i + 3].z * k3v.z + q[i + 3].w * k3v.w;
                }
                const float s = (s0 + s1) + (s2 + s3);
                Sc[kk * QB + tid] = s;
                tmax = fmaxf(tmax, s);
            }

            const float mnew = fmaxf(mrun, tmax);
            const float corr = __expf(mrun - mnew);
            lrun *= corr;
#pragma unroll
            for (int i = 0; i < 16; ++i) {
                acc[i].x *= corr; acc[i].y *= corr; acc[i].z *= corr; acc[i].w *= corr;
            }
            const float4* Vs4 = (const float4*)Vs;
            for (int kk = 0; kk < klim; ++kk) {
                const float p = __expf(Sc[kk * QB + tid] - mnew);
                lrun += p;
                const float4* vr = Vs4 + kk * 16;
#pragma unroll
                for (int i = 0; i < 16; ++i) {
                    acc[i].x = fmaf(p, vr[i].x, acc[i].x);
                    acc[i].y = fmaf(p, vr[i].y, acc[i].y);
                    acc[i].z = fmaf(p, vr[i].z, acc[i].z);
                    acc[i].w = fmaf(p, vr[i].w, acc[i].w);
                }
            }
            mrun = mnew;
        }
        __syncthreads();
    }

    const float inv = 1.f / lrun;
    const size_t base = ((size_t)bb * SS + gq) * DD + h * DH;
#pragma unroll
    for (int i = 0; i < 16; ++i) {
        float v[4] = { acc[i].x * inv, acc[i].y * inv, acc[i].z * inv, acc[i].w * inv };
        ushort4 hh, ll;
        ushort* hp = &hh.x; ushort* lp = &ll.x;
#pragma unroll
        for (int c = 0; c < 4; ++c) {
            __nv_bfloat16 hb = __float2bfloat16(v[c]);
            hp[c] = __bfloat16_as_ushort(hb);
            lp[c] = __bfloat16_as_ushort(__float2bfloat16(v[c] - __bfloat162float(hb)));
        }
        *(ushort4*)(oh + base + i * 4) = hh;
        *(ushort4*)(ol + base + i * 4) = ll;
    }
}

// ---------------------------------------------------------------------------
extern "C" void kernel_launch(void* const* d_in, const int* in_sizes, int n_in,
                              void* d_out, int out_size) {
    const float* queries = (const float*)d_in[0];
    const float* keys    = (const float*)d_in[1];
    const float* values  = (const float*)d_in[2];
    const float* W_Q = (const float*)d_in[3];
    const float* b_Q = (const float*)d_in[4];
    const float* W_K = (const float*)d_in[5];
    const float* b_K = (const float*)d_in[6];
    const float* W_V = (const float*)d_in[7];
    const float* b_V = (const float*)d_in[8];
    const float* W_O = (const float*)d_in[9];
    const float* b_O = (const float*)d_in[10];
    float* out = (float*)d_out;

    float *q_p, *k_p, *v_p;
    cudaGetSymbolAddress((void**)&q_p, g_q);
    cudaGetSymbolAddress((void**)&k_p, g_k);
    cudaGetSymbolAddress((void**)&v_p, g_v);

    __nv_bfloat16 *aqh, *aql, *akh, *akl, *avh, *avl, *ath, *atl;
    __nv_bfloat16 *wqh, *wql, *wkh, *wkl, *wvh, *wvl, *woh, *wol;
    cudaGetSymbolAddress((void**)&aqh, g_aq_h); cudaGetSymbolAddress((void**)&aql, g_aq_l);
    cudaGetSymbolAddress((void**)&akh, g_ak_h); cudaGetSymbolAddress((void**)&akl, g_ak_l);
    cudaGetSymbolAddress((void**)&avh, g_av_h); cudaGetSymbolAddress((void**)&avl, g_av_l);
    cudaGetSymbolAddress((void**)&ath, g_at_h); cudaGetSymbolAddress((void**)&atl, g_at_l);
    cudaGetSymbolAddress((void**)&wqh, g_wq_h); cudaGetSymbolAddress((void**)&wql, g_wq_l);
    cudaGetSymbolAddress((void**)&wkh, g_wk_h); cudaGetSymbolAddress((void**)&wkl, g_wk_l);
    cudaGetSymbolAddress((void**)&wvh, g_wv_h); cudaGetSymbolAddress((void**)&wvl, g_wv_l);
    cudaGetSymbolAddress((void**)&woh, g_wo_h); cudaGetSymbolAddress((void**)&wol, g_wo_l);

    static bool attr_set = false;
    if (!attr_set) {
        cudaFuncSetAttribute(attn_kernel, cudaFuncAttributeMaxDynamicSharedMemorySize, ATTN_SMEM);
        cudaFuncSetAttribute(gemm_mma<0>, cudaFuncAttributeMaxDynamicSharedMemorySize, GSM_TOTAL);
        cudaFuncSetAttribute(gemm_mma<1>, cudaFuncAttributeMaxDynamicSharedMemorySize, GSM_TOTAL);
        attr_set = true;
    }

    const int nAct4 = MM * DD / 4;
    const int nW4   = DD * DD / 4;
    cvt_split<<<(nAct4 + 255) / 256, 256>>>(queries, aqh, aql, nAct4);
    cvt_split<<<(nAct4 + 255) / 256, 256>>>(keys,    akh, akl, nAct4);
    cvt_split<<<(nAct4 + 255) / 256, 256>>>(values,  avh, avl, nAct4);
    cvt_split<<<(nW4 + 255) / 256, 256>>>(W_Q, wqh, wql, nW4);
    cvt_split<<<(nW4 + 255) / 256, 256>>>(W_K, wkh, wkl, nW4);
    cvt_split<<<(nW4 + 255) / 256, 256>>>(W_V, wvh, wvl, nW4);
    cvt_split<<<(nW4 + 255) / 256, 256>>>(W_O, woh, wol, nW4);

    const float qscale = 1.0f / 8.0f;   // 1/sqrt(64)
    dim3 ggrid(MM / 128, DD / 128);     // 32 x 8

    gemm_mma<0><<<ggrid, 256, GSM_TOTAL>>>(aqh, aql, wqh, wql, b_Q, q_p, qscale);
    gemm_mma<0><<<ggrid, 256, GSM_TOTAL>>>(akh, akl, wkh, wkl, b_K, k_p, 1.0f);
    gemm_mma<0><<<ggrid, 256, GSM_TOTAL>>>(avh, avl, wvh, wvl, b_V, v_p, 1.0f);

    dim3 agrid(SS / QB, HH, BB);        // 16 x 16 x 2
    attn_kernel<<<agrid, QB, ATTN_SMEM>>>(q_p, k_p, v_p, ath, atl);

    gemm_mma<1><<<ggrid, 256, GSM_TOTAL>>>(ath, atl, woh, wol, b_O, out, 1.0f);
}

// round 4
// speedup vs baseline: 3.5010x; 2.2222x over previous
#include <cuda_runtime.h>
#include <cuda_bf16.h>
#include <math.h>
#include <stdint.h>

// Problem constants
#define BB 2
#define SS 2048
#define DD 1024
#define HH 16
#define DH 64
#define MM (BB * SS)   // 4096

// ---------------------------------------------------------------------------
// Scratch (device globals; allocation APIs are forbidden)
// ---------------------------------------------------------------------------
// split-bf16 Q/K/V in (B,H,S,DH) layout (written by projection GEMM epilogues)
__device__ __nv_bfloat16 g_qh[MM * DD], g_ql[MM * DD];
__device__ __nv_bfloat16 g_kh[MM * DD], g_kl[MM * DD];
__device__ __nv_bfloat16 g_vh[MM * DD], g_vl[MM * DD];

// split-bf16 GEMM inputs
__device__ __nv_bfloat16 g_aq_h[MM * DD], g_aq_l[MM * DD];
__device__ __nv_bfloat16 g_ak_h[MM * DD], g_ak_l[MM * DD];
__device__ __nv_bfloat16 g_av_h[MM * DD], g_av_l[MM * DD];
__device__ __nv_bfloat16 g_at_h[MM * DD], g_at_l[MM * DD];
__device__ __nv_bfloat16 g_wq_h[DD * DD], g_wq_l[DD * DD];
__device__ __nv_bfloat16 g_wk_h[DD * DD], g_wk_l[DD * DD];
__device__ __nv_bfloat16 g_wv_h[DD * DD], g_wv_l[DD * DD];
__device__ __nv_bfloat16 g_wo_h[DD * DD], g_wo_l[DD * DD];

// ---------------------------------------------------------------------------
// PTX helpers (non-'a'-gated: mma.sync / ldmatrix / cp.async only)
// ---------------------------------------------------------------------------
__device__ __forceinline__ uint32_t smem_u32(const void* p) {
    uint32_t a;
    asm("{ .reg .u64 t; cvta.to.shared.u64 t, %1; cvt.u32.u64 %0, t; }"
        : "=r"(a) : "l"(p));
    return a;
}

__device__ __forceinline__ void cpa16(uint32_t s, const void* g) {
    asm volatile("cp.async.cg.shared.global [%0], [%1], 16;"
                 :: "r"(s), "l"(g) : "memory");
}

__device__ __forceinline__ void ldsm4(uint32_t* r, uint32_t a) {
    asm volatile("ldmatrix.sync.aligned.m8n8.x4.shared.b16 {%0,%1,%2,%3}, [%4];"
                 : "=r"(r[0]), "=r"(r[1]), "=r"(r[2]), "=r"(r[3]) : "r"(a));
}

__device__ __forceinline__ void ldsm4t(uint32_t* r, uint32_t a) {
    asm volatile("ldmatrix.sync.aligned.m8n8.x4.trans.shared.b16 {%0,%1,%2,%3}, [%4];"
                 : "=r"(r[0]), "=r"(r[1]), "=r"(r[2]), "=r"(r[3]) : "r"(a));
}

__device__ __forceinline__ void mma16816(float* d, const uint32_t* a,
                                         uint32_t b0, uint32_t b1) {
    asm volatile(
        "mma.sync.aligned.m16n8k16.row.col.f32.bf16.bf16.f32 "
        "{%0,%1,%2,%3}, {%4,%5,%6,%7}, {%8,%9}, {%0,%1,%2,%3};"
        : "+f"(d[0]), "+f"(d[1]), "+f"(d[2]), "+f"(d[3])
        : "r"(a[0]), "r"(a[1]), "r"(a[2]), "r"(a[3]), "r"(b0), "r"(b1));
}

// split a,b -> packed bf16x2 hi and lo
__device__ __forceinline__ void split2(float a, float b, uint32_t& hi, uint32_t& lo) {
    __nv_bfloat16 ha = __float2bfloat16(a), hb = __float2bfloat16(b);
    __nv_bfloat16 la = __float2bfloat16(a - __bfloat162float(ha));
    __nv_bfloat16 lb = __float2bfloat16(b - __bfloat162float(hb));
    hi = (uint32_t)__bfloat16_as_ushort(ha) | ((uint32_t)__bfloat16_as_ushort(hb) << 16);
    lo = (uint32_t)__bfloat16_as_ushort(la) | ((uint32_t)__bfloat16_as_ushort(lb) << 16);
}

// ---------------------------------------------------------------------------
// fp32 -> (hi, lo) bf16 split
// ---------------------------------------------------------------------------
__global__ __launch_bounds__(256)
void cvt_split(const float* __restrict__ x, __nv_bfloat16* __restrict__ hi,
               __nv_bfloat16* __restrict__ lo, int n4) {
    int i = blockIdx.x * 256 + threadIdx.x;
    if (i >= n4) return;
    float4 v = ((const float4*)x)[i];
    ushort4 h, l;
    {
        __nv_bfloat16 hb = __float2bfloat16(v.x);
        h.x = __bfloat16_as_ushort(hb);
        l.x = __bfloat16_as_ushort(__float2bfloat16(v.x - __bfloat162float(hb)));
    }
    {
        __nv_bfloat16 hb = __float2bfloat16(v.y);
        h.y = __bfloat16_as_ushort(hb);
        l.y = __bfloat16_as_ushort(__float2bfloat16(v.y - __bfloat162float(hb)));
    }
    {
        __nv_bfloat16 hb = __float2bfloat16(v.z);
        h.z = __bfloat16_as_ushort(hb);
        l.z = __bfloat16_as_ushort(__float2bfloat16(v.z - __bfloat162float(hb)));
    }
    {
        __nv_bfloat16 hb = __float2bfloat16(v.w);
        h.w = __bfloat16_as_ushort(hb);
        l.w = __bfloat16_as_ushort(__float2bfloat16(v.w - __bfloat162float(hb)));
    }
    ((ushort4*)hi)[i] = h;
    ((ushort4*)lo)[i] = l;
}

// ---------------------------------------------------------------------------
// Split-bf16 NT GEMM via mma.sync (as R3).
// MODE 0: split-bf16 output to (B,H,S,DH) hi/lo arrays.
// MODE 1: fp32 output row-major (M,N).
// ---------------------------------------------------------------------------
#define BKT 32
#define STG_BYTES 32768
#define OFF_AH 0
#define OFF_AL 8192
#define OFF_BH 16384
#define OFF_BL 24576
#define GSM_TOTAL 65536

template <int MODE>
__global__ __launch_bounds__(256)
void gemm_mma(const __nv_bfloat16* __restrict__ Ah, const __nv_bfloat16* __restrict__ Al,
              const __nv_bfloat16* __restrict__ Bh, const __nv_bfloat16* __restrict__ Bl,
              const float* __restrict__ bias, float* __restrict__ C,
              __nv_bfloat16* __restrict__ Ch, __nv_bfloat16* __restrict__ Cl,
              float scale) {
    extern __shared__ char smc[];
    const uint32_t sb = smem_u32(smc);
    const int tid = threadIdx.x;
    const int lane = tid & 31, wid = tid >> 5;
    const int wm = (wid & 3) * 32;
    const int wn = (wid >> 2) * 64;
    const int m0 = blockIdx.x * 128, n0 = blockIdx.y * 128;

    const int lr = tid >> 2;
    const int lc = tid & 3;

    float d[2][8][4] = {};

#define ISSUE_STAGE(it, sbase)                                                   \
    {                                                                            \
        const int k0 = (it) * BKT;                                               \
        _Pragma("unroll")                                                        \
        for (int rep = 0; rep < 2; ++rep) {                                      \
            const int row = lr + rep * 64;                                       \
            const uint32_t soff = row * 64 + ((lc ^ ((row >> 1) & 3)) << 4);     \
            const size_t ga = (size_t)(m0 + row) * DD + k0 + lc * 8;             \
            const size_t gb = (size_t)(n0 + row) * DD + k0 + lc * 8;             \
            cpa16(sb + (sbase) + OFF_AH + soff, Ah + ga);                        \
            cpa16(sb + (sbase) + OFF_AL + soff, Al + ga);                        \
            cpa16(sb + (sbase) + OFF_BH + soff, Bh + gb);                        \
            cpa16(sb + (sbase) + OFF_BL + soff, Bl + gb);                        \
        }                                                                        \
    }

    ISSUE_STAGE(0, 0);
    asm volatile("cp.async.commit_group;" ::: "memory");
    ISSUE_STAGE(1, STG_BYTES);
    asm volatile("cp.async.commit_group;" ::: "memory");

    for (int it = 0; it < DD / BKT; ++it) {
        asm volatile("cp.async.wait_group 1;" ::: "memory");
        __syncthreads();
        const uint32_t st = sb + (it & 1) * STG_BYTES;

#pragma unroll
        for (int ks = 0; ks < 2; ++ks) {
            uint32_t ah[2][4], al[2][4], bh[4][4], bl[4][4];
#pragma unroll
            for (int mi = 0; mi < 2; ++mi) {
                const int row = wm + mi * 16 + (lane & 15);
                const int ch = ks * 2 + (lane >> 4);
                const uint32_t ad = st + row * 64 + ((ch ^ ((row >> 1) & 3)) << 4);
                ldsm4(ah[mi], ad + OFF_AH);
                ldsm4(al[mi], ad + OFF_AL);
            }
#pragma unroll
            for (int ng = 0; ng < 4; ++ng) {
                const int row = wn + ng * 16 + (lane & 7) + ((lane >> 4) << 3);
                const int ch = ks * 2 + ((lane >> 3) & 1);
                const uint32_t bd = st + row * 64 + ((ch ^ ((row >> 1) & 3)) << 4);
                ldsm4(bh[ng], bd + OFF_BH);
                ldsm4(bl[ng], bd + OFF_BL);
            }
#pragma unroll
            for (int mi = 0; mi < 2; ++mi) {
#pragma unroll
                for (int n8 = 0; n8 < 8; ++n8) {
                    const int ng = n8 >> 1, hf = n8 & 1;
                    float* dd = d[mi][n8];
                    mma16816(dd, ah[mi], bh[ng][hf * 2], bh[ng][hf * 2 + 1]);
                    mma16816(dd, ah[mi], bl[ng][hf * 2], bl[ng][hf * 2 + 1]);
                    mma16816(dd, al[mi], bh[ng][hf * 2], bh[ng][hf * 2 + 1]);
                }
            }
        }
        __syncthreads();
        if (it + 2 < DD / BKT) {
            ISSUE_STAGE(it + 2, (it & 1) * STG_BYTES);
        }
        asm volatile("cp.async.commit_group;" ::: "memory");
    }
#undef ISSUE_STAGE

    const int row = lane >> 2, colp = (lane & 3) * 2;
#pragma unroll
    for (int mi = 0; mi < 2; ++mi) {
#pragma unroll
        for (int n8 = 0; n8 < 8; ++n8) {
            const float* dd = d[mi][n8];
            const int n = n0 + wn + n8 * 8 + colp;
            const float2 b2 = *(const float2*)(bias + n);
#pragma unroll
            for (int rh = 0; rh < 2; ++rh) {
                const int m = m0 + wm + mi * 16 + row + rh * 8;
                float rx = (dd[rh * 2 + 0] + b2.x) * scale;
                float ry = (dd[rh * 2 + 1] + b2.y) * scale;
                if (MODE == 0) {
                    const int bb = m >> 11, s = m & (SS - 1);
                    const int h = n >> 6, dh = n & (DH - 1);
                    const size_t idx = ((size_t)(bb * HH + h) * SS + s) * DH + dh;
                    uint32_t hi, lo;
                    split2(rx, ry, hi, lo);
                    *(uint32_t*)(Ch + idx) = hi;
                    *(uint32_t*)(Cl + idx) = lo;
                } else {
                    float2 r2 = make_float2(rx, ry);
                    *(float2*)(C + (size_t)m * DD + n) = r2;
                }
            }
        }
    }
}

// ---------------------------------------------------------------------------
// Flash attention via mma.sync, split-bf16 QK^T and PV.
// Block = 128 queries (8 warps x 16 rows). Key tiles of 64, 2-stage cp.async.
// smem per stage: Kh(8K) Kl(8K) Vh(8K) Vl(8K) = 32KB; 2 stages = 64KB.
// ---------------------------------------------------------------------------
#define ATT_SMEM 65536

__global__ __launch_bounds__(256)
void attn_mma(const __nv_bfloat16* __restrict__ qh_g, const __nv_bfloat16* __restrict__ ql_g,
              const __nv_bfloat16* __restrict__ kh_g, const __nv_bfloat16* __restrict__ kl_g,
              const __nv_bfloat16* __restrict__ vh_g, const __nv_bfloat16* __restrict__ vl_g,
              __nv_bfloat16* __restrict__ oh_g, __nv_bfloat16* __restrict__ ol_g) {
    extern __shared__ char smc[];
    const uint32_t sb = smem_u32(smc);
    const int tid = threadIdx.x, lane = tid & 31, w = tid >> 5;
    const int qt = gridDim.x - 1 - (int)blockIdx.x;   // heavy blocks first
    const int h = blockIdx.y, bb = blockIdx.z;
    const int q0 = qt * 128;
    const size_t hb = (size_t)(bb * HH + h) * SS * DH;
    const int wr0 = q0 + w * 16;
    const int nkt = qt * 2 + 2;

    // Q fragments (held in registers for whole kernel)
    uint32_t qfh[4][4], qfl[4][4];
    {
        const int r = lane >> 2, c2 = (lane & 3) * 2;
#pragma unroll
        for (int f = 0; f < 4; ++f) {
#pragma unroll
            for (int idx = 0; idx < 4; ++idx) {
                const int rr = r + (idx & 1) * 8;
                const int kk = f * 16 + c2 + (idx >> 1) * 8;
                const size_t off = hb + (size_t)(wr0 + rr) * DH + kk;
                qfh[f][idx] = *(const uint32_t*)(qh_g + off);
                qfl[f][idx] = *(const uint32_t*)(ql_g + off);
            }
        }
    }

    float O[8][4] = {};
    float m0v = -1e30f, m1v = -1e30f, l0 = 0.f, l1 = 0.f;

    const __nv_bfloat16* srcs[4] = { kh_g + hb, kl_g + hb, vh_g + hb, vl_g + hb };

#define AISSUE(kt, sbase)                                                        \
    {                                                                            \
        const int kb_ = (kt) * 64;                                               \
        _Pragma("unroll")                                                        \
        for (int t = 0; t < 8; ++t) {                                            \
            const int c = tid + t * 256;                                         \
            const int arr = c >> 9;                                              \
            const int row = (c >> 3) & 63;                                       \
            const int ch = c & 7;                                                \
            const uint32_t dst = sb + (sbase) + arr * 8192 + row * 128           \
                                 + ((ch ^ (row & 7)) << 4);                      \
            cpa16(dst, srcs[arr] + (size_t)(kb_ + row) * DH + ch * 8);           \
        }                                                                        \
    }

    AISSUE(0, 0);
    asm volatile("cp.async.commit_group;" ::: "memory");

    for (int it = 0; it < nkt; ++it) {
        if (it + 1 < nkt) {
            AISSUE(it + 1, ((it + 1) & 1) * 32768);
            asm volatile("cp.async.commit_group;" ::: "memory");
            asm volatile("cp.async.wait_group 1;" ::: "memory");
        } else {
            asm volatile("cp.async.wait_group 0;" ::: "memory");
        }
        __syncthreads();

        const int kb = it * 64;
        if (kb <= wr0 + 15) {
            const uint32_t st = sb + (it & 1) * 32768;
            float s[8][4] = {};

            // QK^T (3-MMA split)
            const int srow_b = (lane & 7) + ((lane >> 4) << 3);
            const int sch_b = (lane >> 3) & 1;
#pragma unroll
            for (int f = 0; f < 4; ++f) {
#pragma unroll
                for (int ng = 0; ng < 4; ++ng) {
                    const int row = ng * 16 + srow_b;
                    const int ch = f * 2 + sch_b;
                    const uint32_t ad = st + row * 128 + ((ch ^ (row & 7)) << 4);
                    uint32_t kh4[4], kl4[4];
                    ldsm4(kh4, ad);            // Kh
                    ldsm4(kl4, ad + 8192);     // Kl
#pragma unroll
                    for (int hf = 0; hf < 2; ++hf) {
                        float* ss = s[ng * 2 + hf];
                        mma16816(ss, qfh[f], kh4[hf * 2], kh4[hf * 2 + 1]);
                        mma16816(ss, qfh[f], kl4[hf * 2], kl4[hf * 2 + 1]);
                        mma16816(ss, qfl[f], kh4[hf * 2], kh4[hf * 2 + 1]);
                    }
                }
            }

            // causal mask on diagonal-crossing tiles
            if (kb + 63 > wr0) {
                const int r0g = wr0 + (lane >> 2), r1g = r0g + 8;
#pragma unroll
                for (int n8 = 0; n8 < 8; ++n8) {
                    const int c0 = kb + n8 * 8 + (lane & 3) * 2;
                    if (c0 > r0g)     s[n8][0] = -1e30f;
                    if (c0 + 1 > r0g) s[n8][1] = -1e30f;
                    if (c0 > r1g)     s[n8][2] = -1e30f;
                    if (c0 + 1 > r1g) s[n8][3] = -1e30f;
                }
            }

            // row max (reduce across the 4 lanes of each row quad)
            float t0 = -1e30f, t1 = -1e30f;
#pragma unroll
            for (int n8 = 0; n8 < 8; ++n8) {
                t0 = fmaxf(t0, fmaxf(s[n8][0], s[n8][1]));
                t1 = fmaxf(t1, fmaxf(s[n8][2], s[n8][3]));
            }
            t0 = fmaxf(t0, __shfl_xor_sync(0xffffffff, t0, 1));
            t0 = fmaxf(t0, __shfl_xor_sync(0xffffffff, t0, 2));
            t1 = fmaxf(t1, __shfl_xor_sync(0xffffffff, t1, 1));
            t1 = fmaxf(t1, __shfl_xor_sync(0xffffffff, t1, 2));

            const float mn0 = fmaxf(m0v, t0), mn1 = fmaxf(m1v, t1);
            const float cr0 = __expf(m0v - mn0), cr1 = __expf(m1v - mn1);
            m0v = mn0; m1v = mn1;
            l0 *= cr0; l1 *= cr1;
#pragma unroll
            for (int n8 = 0; n8 < 8; ++n8) {
                O[n8][0] *= cr0; O[n8][1] *= cr0;
                O[n8][2] *= cr1; O[n8][3] *= cr1;
            }

            // P = exp(s - m), split to bf16 hi/lo A-fragments
            uint32_t ph[4][4], pl[4][4];
#pragma unroll
            for (int g = 0; g < 4; ++g) {
#pragma unroll
                for (int hf = 0; hf < 2; ++hf) {
                    const float* ss = s[g * 2 + hf];
                    const float p0 = __expf(ss[0] - m0v);
                    const float p1 = __expf(ss[1] - m0v);
                    const float p2 = __expf(ss[2] - m1v);
                    const float p3 = __expf(ss[3] - m1v);
                    l0 += p0 + p1;
                    l1 += p2 + p3;
                    split2(p0, p1, ph[g][hf * 2], pl[g][hf * 2]);
                    split2(p2, p3, ph[g][hf * 2 + 1], pl[g][hf * 2 + 1]);
                }
            }

            // PV (3-MMA split), V via ldmatrix.trans
            const int vrow_b = (lane & 7) + ((lane >> 3) & 1) * 8;
            const int vch_b = lane >> 4;
#pragma unroll
            for (int g = 0; g < 4; ++g) {
                const int row = g * 16 + vrow_b;
#pragma unroll
                for (int no = 0; no < 4; ++no) {
                    const int ch = no * 2 + vch_b;
                    const uint32_t ad = st + 16384 + row * 128 + ((ch ^ (row & 7)) << 4);
                    uint32_t vh4[4], vl4[4];
                    ldsm4t(vh4, ad);           // Vh
                    ldsm4t(vl4, ad + 8192);    // Vl
                    float* o0 = O[no * 2];
                    float* o1 = O[no * 2 + 1];
                    mma16816(o0, ph[g], vh4[0], vh4[1]);
                    mma16816(o0, ph[g], vl4[0], vl4[1]);
                    mma16816(o0, pl[g], vh4[0], vh4[1]);
                    mma16816(o1, ph[g], vh4[2], vh4[3]);
                    mma16816(o1, ph[g], vl4[2], vl4[3]);
                    mma16816(o1, pl[g], vh4[2], vh4[3]);
                }
            }
        }
        __syncthreads();
    }
#undef AISSUE

    // finalize: reduce l across row quad, scale, split-store to merged layout
    l0 += __shfl_xor_sync(0xffffffff, l0, 1);
    l0 += __shfl_xor_sync(0xffffffff, l0, 2);
    l1 += __shfl_xor_sync(0xffffffff, l1, 1);
    l1 += __shfl_xor_sync(0xffffffff, l1, 2);
    const float inv0 = 1.f / l0, inv1 = 1.f / l1;

    const int r = lane >> 2, c2 = (lane & 3) * 2;
    const size_t ob0 = ((size_t)bb * SS + wr0 + r) * DD + h * DH;
    const size_t ob1 = ((size_t)bb * SS + wr0 + r + 8) * DD + h * DH;
#pragma unroll
    for (int n8 = 0; n8 < 8; ++n8) {
        const int col = n8 * 8 + c2;
        uint32_t hi, lo;
        split2(O[n8][0] * inv0, O[n8][1] * inv0, hi, lo);
        *(uint32_t*)(oh_g + ob0 + col) = hi;
        *(uint32_t*)(ol_g + ob0 + col) = lo;
        split2(O[n8][2] * inv1, O[n8][3] * inv1, hi, lo);
        *(uint32_t*)(oh_g + ob1 + col) = hi;
        *(uint32_t*)(ol_g + ob1 + col) = lo;
    }
}

// ---------------------------------------------------------------------------
extern "C" void kernel_launch(void* const* d_in, const int* in_sizes, int n_in,
                              void* d_out, int out_size) {
    const float* queries = (const float*)d_in[0];
    const float* keys    = (const float*)d_in[1];
    const float* values  = (const float*)d_in[2];
    const float* W_Q = (const float*)d_in[3];
    const float* b_Q = (const float*)d_in[4];
    const float* W_K = (const float*)d_in[5];
    const float* b_K = (const float*)d_in[6];
    const float* W_V = (const float*)d_in[7];
    const float* b_V = (const float*)d_in[8];
    const float* W_O = (const float*)d_in[9];
    const float* b_O = (const float*)d_in[10];
    float* out = (float*)d_out;

    __nv_bfloat16 *qh, *ql, *kh, *kl, *vh, *vl;
    cudaGetSymbolAddress((void**)&qh, g_qh); cudaGetSymbolAddress((void**)&ql, g_ql);
    cudaGetSymbolAddress((void**)&kh, g_kh); cudaGetSymbolAddress((void**)&kl, g_kl);
    cudaGetSymbolAddress((void**)&vh, g_vh); cudaGetSymbolAddress((void**)&vl, g_vl);

    __nv_bfloat16 *aqh, *aql, *akh, *akl, *avh, *avl, *ath, *atl;
    __nv_bfloat16 *wqh, *wql, *wkh, *wkl, *wvh, *wvl, *woh, *wol;
    cudaGetSymbolAddress((void**)&aqh, g_aq_h); cudaGetSymbolAddress((void**)&aql, g_aq_l);
    cudaGetSymbolAddress((void**)&akh, g_ak_h); cudaGetSymbolAddress((void**)&akl, g_ak_l);
    cudaGetSymbolAddress((void**)&avh, g_av_h); cudaGetSymbolAddress((void**)&avl, g_av_l);
    cudaGetSymbolAddress((void**)&ath, g_at_h); cudaGetSymbolAddress((void**)&atl, g_at_l);
    cudaGetSymbolAddress((void**)&wqh, g_wq_h); cudaGetSymbolAddress((void**)&wql, g_wq_l);
    cudaGetSymbolAddress((void**)&wkh, g_wk_h); cudaGetSymbolAddress((void**)&wkl, g_wk_l);
    cudaGetSymbolAddress((void**)&wvh, g_wv_h); cudaGetSymbolAddress((void**)&wvl, g_wv_l);
    cudaGetSymbolAddress((void**)&woh, g_wo_h); cudaGetSymbolAddress((void**)&wol, g_wo_l);

    static bool attr_set = false;
    if (!attr_set) {
        cudaFuncSetAttribute(gemm_mma<0>, cudaFuncAttributeMaxDynamicSharedMemorySize, GSM_TOTAL);
        cudaFuncSetAttribute(gemm_mma<1>, cudaFuncAttributeMaxDynamicSharedMemorySize, GSM_TOTAL);
        cudaFuncSetAttribute(attn_mma, cudaFuncAttributeMaxDynamicSharedMemorySize, ATT_SMEM);
        attr_set = true;
    }

    const int nAct4 = MM * DD / 4;
    const int nW4   = DD * DD / 4;
    cvt_split<<<(nAct4 + 255) / 256, 256>>>(queries, aqh, aql, nAct4);
    cvt_split<<<(nAct4 + 255) / 256, 256>>>(keys,    akh, akl, nAct4);
    cvt_split<<<(nAct4 + 255) / 256, 256>>>(values,  avh, avl, nAct4);
    cvt_split<<<(nW4 + 255) / 256, 256>>>(W_Q, wqh, wql, nW4);
    cvt_split<<<(nW4 + 255) / 256, 256>>>(W_K, wkh, wkl, nW4);
    cvt_split<<<(nW4 + 255) / 256, 256>>>(W_V, wvh, wvl, nW4);
    cvt_split<<<(nW4 + 255) / 256, 256>>>(W_O, woh, wol, nW4);

    const float qscale = 1.0f / 8.0f;   // 1/sqrt(64)
    dim3 ggrid(MM / 128, DD / 128);     // 32 x 8

    gemm_mma<0><<<ggrid, 256, GSM_TOTAL>>>(aqh, aql, wqh, wql, b_Q, nullptr, qh, ql, qscale);
    gemm_mma<0><<<ggrid, 256, GSM_TOTAL>>>(akh, akl, wkh, wkl, b_K, nullptr, kh, kl, 1.0f);
    gemm_mma<0><<<ggrid, 256, GSM_TOTAL>>>(avh, avl, wvh, wvl, b_V, nullptr, vh, vl, 1.0f);

    dim3 agrid(SS / 128, HH, BB);       // 16 x 16 x 2
    attn_mma<<<agrid, 256, ATT_SMEM>>>(qh, ql, kh, kl, vh, vl, ath, atl);

    gemm_mma<1><<<ggrid, 256, GSM_TOTAL>>>(ath, atl, woh, wol, b_O, out, nullptr, nullptr, 1.0f);
}

// round 5
// speedup vs baseline: 3.8327x; 1.0948x over previous
#include <cuda_runtime.h>
#include <cuda_bf16.h>
#include <math.h>
#include <stdint.h>

// Problem constants
#define BB 2
#define SS 2048
#define DD 1024
#define HH 16
#define DH 64
#define MM (BB * SS)   // 4096

// ---------------------------------------------------------------------------
// Scratch (device globals; allocation APIs are forbidden)
// ---------------------------------------------------------------------------
__device__ __nv_bfloat16 g_qh[MM * DD], g_ql[MM * DD];
__device__ __nv_bfloat16 g_kh[MM * DD], g_kl[MM * DD];
__device__ __nv_bfloat16 g_vh[MM * DD], g_vl[MM * DD];

__device__ __nv_bfloat16 g_aq_h[MM * DD], g_aq_l[MM * DD];
__device__ __nv_bfloat16 g_ak_h[MM * DD], g_ak_l[MM * DD];
__device__ __nv_bfloat16 g_av_h[MM * DD], g_av_l[MM * DD];
__device__ __nv_bfloat16 g_at_h[MM * DD], g_at_l[MM * DD];
__device__ __nv_bfloat16 g_wq_h[DD * DD], g_wq_l[DD * DD];
__device__ __nv_bfloat16 g_wk_h[DD * DD], g_wk_l[DD * DD];
__device__ __nv_bfloat16 g_wv_h[DD * DD], g_wv_l[DD * DD];
__device__ __nv_bfloat16 g_wo_h[DD * DD], g_wo_l[DD * DD];

// ---------------------------------------------------------------------------
// PTX helpers (non-'a'-gated: mma.sync / ldmatrix / cp.async only)
// ---------------------------------------------------------------------------
__device__ __forceinline__ uint32_t smem_u32(const void* p) {
    uint32_t a;
    asm("{ .reg .u64 t; cvta.to.shared.u64 t, %1; cvt.u32.u64 %0, t; }"
        : "=r"(a) : "l"(p));
    return a;
}

__device__ __forceinline__ void cpa16(uint32_t s, const void* g) {
    asm volatile("cp.async.cg.shared.global [%0], [%1], 16;"
                 :: "r"(s), "l"(g) : "memory");
}

__device__ __forceinline__ void ldsm4(uint32_t* r, uint32_t a) {
    asm volatile("ldmatrix.sync.aligned.m8n8.x4.shared.b16 {%0,%1,%2,%3}, [%4];"
                 : "=r"(r[0]), "=r"(r[1]), "=r"(r[2]), "=r"(r[3]) : "r"(a));
}

__device__ __forceinline__ void ldsm4t(uint32_t* r, uint32_t a) {
    asm volatile("ldmatrix.sync.aligned.m8n8.x4.trans.shared.b16 {%0,%1,%2,%3}, [%4];"
                 : "=r"(r[0]), "=r"(r[1]), "=r"(r[2]), "=r"(r[3]) : "r"(a));
}

__device__ __forceinline__ void mma16816(float* d, const uint32_t* a,
                                         uint32_t b0, uint32_t b1) {
    asm volatile(
        "mma.sync.aligned.m16n8k16.row.col.f32.bf16.bf16.f32 "
        "{%0,%1,%2,%3}, {%4,%5,%6,%7}, {%8,%9}, {%0,%1,%2,%3};"
        : "+f"(d[0]), "+f"(d[1]), "+f"(d[2]), "+f"(d[3])
        : "r"(a[0]), "r"(a[1]), "r"(a[2]), "r"(a[3]), "r"(b0), "r"(b1));
}

__device__ __forceinline__ void split2(float a, float b, uint32_t& hi, uint32_t& lo) {
    __nv_bfloat16 ha = __float2bfloat16(a), hb = __float2bfloat16(b);
    __nv_bfloat16 la = __float2bfloat16(a - __bfloat162float(ha));
    __nv_bfloat16 lb = __float2bfloat16(b - __bfloat162float(hb));
    hi = (uint32_t)__bfloat16_as_ushort(ha) | ((uint32_t)__bfloat16_as_ushort(hb) << 16);
    lo = (uint32_t)__bfloat16_as_ushort(la) | ((uint32_t)__bfloat16_as_ushort(lb) << 16);
}

// ---------------------------------------------------------------------------
// fp32 -> (hi, lo) bf16 split; grid.y selects among up to 4 tensors.
// ---------------------------------------------------------------------------
__global__ __launch_bounds__(256)
void cvt_split4(const float* __restrict__ x0, __nv_bfloat16* h0, __nv_bfloat16* l0,
                const float* __restrict__ x1, __nv_bfloat16* h1, __nv_bfloat16* l1,
                const float* __restrict__ x2, __nv_bfloat16* h2, __nv_bfloat16* l2,
                const float* __restrict__ x3, __nv_bfloat16* h3, __nv_bfloat16* l3,
                int n4) {
    const int sel = blockIdx.y;
    const float* x = sel == 0 ? x0 : sel == 1 ? x1 : sel == 2 ? x2 : x3;
    __nv_bfloat16* hi = sel == 0 ? h0 : sel == 1 ? h1 : sel == 2 ? h2 : h3;
    __nv_bfloat16* lo = sel == 0 ? l0 : sel == 1 ? l1 : sel == 2 ? l2 : l3;
    int i = blockIdx.x * 256 + threadIdx.x;
    if (i >= n4) return;
    float4 v = ((const float4*)x)[i];
    ushort4 h, l;
    {
        __nv_bfloat16 hb = __float2bfloat16(v.x);
        h.x = __bfloat16_as_ushort(hb);
        l.x = __bfloat16_as_ushort(__float2bfloat16(v.x - __bfloat162float(hb)));
    }
    {
        __nv_bfloat16 hb = __float2bfloat16(v.y);
        h.y = __bfloat16_as_ushort(hb);
        l.y = __bfloat16_as_ushort(__float2bfloat16(v.y - __bfloat162float(hb)));
    }
    {
        __nv_bfloat16 hb = __float2bfloat16(v.z);
        h.z = __bfloat16_as_ushort(hb);
        l.z = __bfloat16_as_ushort(__float2bfloat16(v.z - __bfloat162float(hb)));
    }
    {
        __nv_bfloat16 hb = __float2bfloat16(v.w);
        h.w = __bfloat16_as_ushort(hb);
        l.w = __bfloat16_as_ushort(__float2bfloat16(v.w - __bfloat162float(hb)));
    }
    ((ushort4*)hi)[i] = h;
    ((ushort4*)lo)[i] = l;
}

// ---------------------------------------------------------------------------
// Split-bf16 NT GEMM, 3-stage cp.async pipeline, one __syncthreads per k-tile.
// Tile 128x128x32, 256 threads (8 warps 4x2), warp tile 32x64.
// MODE 0: split-bf16 output to (B,H,S,DH); MODE 1: fp32 row-major.
// ---------------------------------------------------------------------------
#define BKT 32
#define STG_BYTES 32768
#define OFF_AH 0
#define OFF_AL 8192
#define OFF_BH 16384
#define OFF_BL 24576
#define GSM_TOTAL (3 * STG_BYTES)   // 96 KB

template <int MODE>
__global__ __launch_bounds__(256, 2)
void gemm_mma(const __nv_bfloat16* __restrict__ Ah, const __nv_bfloat16* __restrict__ Al,
              const __nv_bfloat16* __restrict__ Bh, const __nv_bfloat16* __restrict__ Bl,
              const float* __restrict__ bias, float* __restrict__ C,
              __nv_bfloat16* __restrict__ Ch, __nv_bfloat16* __restrict__ Cl,
              float scale) {
    extern __shared__ char smc[];
    const uint32_t sb = smem_u32(smc);
    const int tid = threadIdx.x;
    const int lane = tid & 31, wid = tid >> 5;
    const int wm = (wid & 3) * 32;
    const int wn = (wid >> 2) * 64;
    const int m0 = blockIdx.x * 128, n0 = blockIdx.y * 128;

    const int lr = tid >> 2;
    const int lc = tid & 3;

    float d[2][8][4] = {};

#define ISSUE_STAGE(it, sbase)                                                   \
    {                                                                            \
        const int k0 = (it) * BKT;                                               \
        _Pragma("unroll")                                                        \
        for (int rep = 0; rep < 2; ++rep) {                                      \
            const int row = lr + rep * 64;                                       \
            const uint32_t soff = row * 64 + ((lc ^ ((row >> 1) & 3)) << 4);     \
            const size_t ga = (size_t)(m0 + row) * DD + k0 + lc * 8;             \
            const size_t gb = (size_t)(n0 + row) * DD + k0 + lc * 8;             \
            cpa16(sb + (sbase) + OFF_AH + soff, Ah + ga);                        \
            cpa16(sb + (sbase) + OFF_AL + soff, Al + ga);                        \
            cpa16(sb + (sbase) + OFF_BH + soff, Bh + gb);                        \
            cpa16(sb + (sbase) + OFF_BL + soff, Bl + gb);                        \
        }                                                                        \
    }

    ISSUE_STAGE(0, 0);
    asm volatile("cp.async.commit_group;" ::: "memory");
    ISSUE_STAGE(1, STG_BYTES);
    asm volatile("cp.async.commit_group;" ::: "memory");

    int stq = 0;   // (it) % 3
    int stw = 2;   // (it+2) % 3
    for (int it = 0; it < DD / BKT; ++it) {
        asm volatile("cp.async.wait_group 1;" ::: "memory");
        __syncthreads();
        if (it + 2 < DD / BKT) {
            ISSUE_STAGE(it + 2, stw * STG_BYTES);
        }
        asm volatile("cp.async.commit_group;" ::: "memory");

        const uint32_t st = sb + stq * STG_BYTES;
#pragma unroll
        for (int ks = 0; ks < 2; ++ks) {
            uint32_t ah[2][4], al[2][4], bh[4][4], bl[4][4];
#pragma unroll
            for (int mi = 0; mi < 2; ++mi) {
                const int row = wm + mi * 16 + (lane & 15);
                const int ch = ks * 2 + (lane >> 4);
                const uint32_t ad = st + row * 64 + ((ch ^ ((row >> 1) & 3)) << 4);
                ldsm4(ah[mi], ad + OFF_AH);
                ldsm4(al[mi], ad + OFF_AL);
            }
#pragma unroll
            for (int ng = 0; ng < 4; ++ng) {
                const int row = wn + ng * 16 + (lane & 7) + ((lane >> 4) << 3);
                const int ch = ks * 2 + ((lane >> 3) & 1);
                const uint32_t bd = st + row * 64 + ((ch ^ ((row >> 1) & 3)) << 4);
                ldsm4(bh[ng], bd + OFF_BH);
                ldsm4(bl[ng], bd + OFF_BL);
            }
#pragma unroll
            for (int mi = 0; mi < 2; ++mi) {
#pragma unroll
                for (int n8 = 0; n8 < 8; ++n8) {
                    const int ng = n8 >> 1, hf = n8 & 1;
                    float* dd = d[mi][n8];
                    mma16816(dd, ah[mi], bh[ng][hf * 2], bh[ng][hf * 2 + 1]);
                    mma16816(dd, ah[mi], bl[ng][hf * 2], bl[ng][hf * 2 + 1]);
                    mma16816(dd, al[mi], bh[ng][hf * 2], bh[ng][hf * 2 + 1]);
                }
            }
        }
        stq = stq == 2 ? 0 : stq + 1;
        stw = stw == 2 ? 0 : stw + 1;
    }
#undef ISSUE_STAGE

    const int row = lane >> 2, colp = (lane & 3) * 2;
#pragma unroll
    for (int mi = 0; mi < 2; ++mi) {
#pragma unroll
        for (int n8 = 0; n8 < 8; ++n8) {
            const float* dd = d[mi][n8];
            const int n = n0 + wn + n8 * 8 + colp;
            const float2 b2 = *(const float2*)(bias + n);
#pragma unroll
            for (int rh = 0; rh < 2; ++rh) {
                const int m = m0 + wm + mi * 16 + row + rh * 8;
                float rx = (dd[rh * 2 + 0] + b2.x) * scale;
                float ry = (dd[rh * 2 + 1] + b2.y) * scale;
                if (MODE == 0) {
                    const int bb = m >> 11, s = m & (SS - 1);
                    const int h = n >> 6, dh = n & (DH - 1);
                    const size_t idx = ((size_t)(bb * HH + h) * SS + s) * DH + dh;
                    uint32_t hi, lo;
                    split2(rx, ry, hi, lo);
                    *(uint32_t*)(Ch + idx) = hi;
                    *(uint32_t*)(Cl + idx) = lo;
                } else {
                    float2 r2 = make_float2(rx, ry);
                    *(float2*)(C + (size_t)m * DD + n) = r2;
                }
            }
        }
    }
}

// ---------------------------------------------------------------------------
// Flash attention via mma.sync, split-bf16 QK^T and PV.
// 3-stage cp.async pipeline (stages of 32KB: Kh/Kl/Vh/Vl), one sync per tile.
// ---------------------------------------------------------------------------
#define ATT_STG 32768
#define ATT_SMEM (3 * ATT_STG)   // 96 KB

__global__ __launch_bounds__(256)
void attn_mma(const __nv_bfloat16* __restrict__ qh_g, const __nv_bfloat16* __restrict__ ql_g,
              const __nv_bfloat16* __restrict__ kh_g, const __nv_bfloat16* __restrict__ kl_g,
              const __nv_bfloat16* __restrict__ vh_g, const __nv_bfloat16* __restrict__ vl_g,
              __nv_bfloat16* __restrict__ oh_g, __nv_bfloat16* __restrict__ ol_g) {
    extern __shared__ char smc[];
    const uint32_t sb = smem_u32(smc);
    const int tid = threadIdx.x, lane = tid & 31, w = tid >> 5;
    const int qt = gridDim.x - 1 - (int)blockIdx.x;   // heavy blocks first
    const int h = blockIdx.y, bb = blockIdx.z;
    const int q0 = qt * 128;
    const size_t hb = (size_t)(bb * HH + h) * SS * DH;
    const int wr0 = q0 + w * 16;
    const int nkt = qt * 2 + 2;

    uint32_t qfh[4][4], qfl[4][4];
    {
        const int r = lane >> 2, c2 = (lane & 3) * 2;
#pragma unroll
        for (int f = 0; f < 4; ++f) {
#pragma unroll
            for (int idx = 0; idx < 4; ++idx) {
                const int rr = r + (idx & 1) * 8;
                const int kk = f * 16 + c2 + (idx >> 1) * 8;
                const size_t off = hb + (size_t)(wr0 + rr) * DH + kk;
                qfh[f][idx] = *(const uint32_t*)(qh_g + off);
                qfl[f][idx] = *(const uint32_t*)(ql_g + off);
            }
        }
    }

    float O[8][4] = {};
    float m0v = -1e30f, m1v = -1e30f, l0 = 0.f, l1 = 0.f;

    const __nv_bfloat16* srcs[4] = { kh_g + hb, kl_g + hb, vh_g + hb, vl_g + hb };

#define AISSUE(kt, sbase)                                                        \
    {                                                                            \
        const int kb_ = (kt) * 64;                                               \
        _Pragma("unroll")                                                        \
        for (int t = 0; t < 8; ++t) {                                            \
            const int c = tid + t * 256;                                         \
            const int arr = c >> 9;                                              \
            const int row = (c >> 3) & 63;                                       \
            const int ch = c & 7;                                                \
            const uint32_t dst = sb + (sbase) + arr * 8192 + row * 128           \
                                 + ((ch ^ (row & 7)) << 4);                      \
            cpa16(dst, srcs[arr] + (size_t)(kb_ + row) * DH + ch * 8);           \
        }                                                                        \
    }

    AISSUE(0, 0);
    asm volatile("cp.async.commit_group;" ::: "memory");
    AISSUE(1, ATT_STG);
    asm volatile("cp.async.commit_group;" ::: "memory");

    int stq = 0, stw = 2;
    for (int it = 0; it < nkt; ++it) {
        asm volatile("cp.async.wait_group 1;" ::: "memory");
        __syncthreads();
        if (it + 2 < nkt) {
            AISSUE(it + 2, stw * ATT_STG);
        }
        asm volatile("cp.async.commit_group;" ::: "memory");

        const int kb = it * 64;
        if (kb <= wr0 + 15) {
            const uint32_t st = sb + stq * ATT_STG;
            float s[8][4] = {};

            const int srow_b = (lane & 7) + ((lane >> 4) << 3);
            const int sch_b = (lane >> 3) & 1;
#pragma unroll
            for (int f = 0; f < 4; ++f) {
#pragma unroll
                for (int ng = 0; ng < 4; ++ng) {
                    const int row = ng * 16 + srow_b;
                    const int ch = f * 2 + sch_b;
                    const uint32_t ad = st + row * 128 + ((ch ^ (row & 7)) << 4);
                    uint32_t kh4[4], kl4[4];
                    ldsm4(kh4, ad);
                    ldsm4(kl4, ad + 8192);
#pragma unroll
                    for (int hf = 0; hf < 2; ++hf) {
                        float* ss = s[ng * 2 + hf];
                        mma16816(ss, qfh[f], kh4[hf * 2], kh4[hf * 2 + 1]);
                        mma16816(ss, qfh[f], kl4[hf * 2], kl4[hf * 2 + 1]);
                        mma16816(ss, qfl[f], kh4[hf * 2], kh4[hf * 2 + 1]);
                    }
                }
            }

            if (kb + 63 > wr0) {
                const int r0g = wr0 + (lane >> 2), r1g = r0g + 8;
#pragma unroll
                for (int n8 = 0; n8 < 8; ++n8) {
                    const int c0 = kb + n8 * 8 + (lane & 3) * 2;
                    if (c0 > r0g)     s[n8][0] = -1e30f;
                    if (c0 + 1 > r0g) s[n8][1] = -1e30f;
                    if (c0 > r1g)     s[n8][2] = -1e30f;
                    if (c0 + 1 > r1g) s[n8][3] = -1e30f;
                }
            }

            float t0 = -1e30f, t1 = -1e30f;
#pragma unroll
            for (int n8 = 0; n8 < 8; ++n8) {
                t0 = fmaxf(t0, fmaxf(s[n8][0], s[n8][1]));
                t1 = fmaxf(t1, fmaxf(s[n8][2], s[n8][3]));
            }
            t0 = fmaxf(t0, __shfl_xor_sync(0xffffffff, t0, 1));
            t0 = fmaxf(t0, __shfl_xor_sync(0xffffffff, t0, 2));
            t1 = fmaxf(t1, __shfl_xor_sync(0xffffffff, t1, 1));
            t1 = fmaxf(t1, __shfl_xor_sync(0xffffffff, t1, 2));

            const float mn0 = fmaxf(m0v, t0), mn1 = fmaxf(m1v, t1);
            const float cr0 = __expf(m0v - mn0), cr1 = __expf(m1v - mn1);
            m0v = mn0; m1v = mn1;
            l0 *= cr0; l1 *= cr1;
#pragma unroll
            for (int n8 = 0; n8 < 8; ++n8) {
                O[n8][0] *= cr0; O[n8][1] *= cr0;
                O[n8][2] *= cr1; O[n8][3] *= cr1;
            }

            uint32_t ph[4][4], pl[4][4];
#pragma unroll
            for (int g = 0; g < 4; ++g) {
#pragma unroll
                for (int hf = 0; hf < 2; ++hf) {
                    const float* ss = s[g * 2 + hf];
                    const float p0 = __expf(ss[0] - m0v);
                    const float p1 = __expf(ss[1] - m0v);
                    const float p2 = __expf(ss[2] - m1v);
                    const float p3 = __expf(ss[3] - m1v);
                    l0 += p0 + p1;
                    l1 += p2 + p3;
                    split2(p0, p1, ph[g][hf * 2], pl[g][hf * 2]);
                    split2(p2, p3, ph[g][hf * 2 + 1], pl[g][hf * 2 + 1]);
                }
            }

            const int vrow_b = (lane & 7) + ((lane >> 3) & 1) * 8;
            const int vch_b = lane >> 4;
#pragma unroll
            for (int g = 0; g < 4; ++g) {
                const int row = g * 16 + vrow_b;
#pragma unroll
                for (int no = 0; no < 4; ++no) {
                    const int ch = no * 2 + vch_b;
                    const uint32_t ad = st + 16384 + row * 128 + ((ch ^ (row & 7)) << 4);
                    uint32_t vh4[4], vl4[4];
                    ldsm4t(vh4, ad);
                    ldsm4t(vl4, ad + 8192);
                    float* o0 = O[no * 2];
                    float* o1 = O[no * 2 + 1];
                    mma16816(o0, ph[g], vh4[0], vh4[1]);
                    mma16816(o0, ph[g], vl4[0], vl4[1]);
                    mma16816(o0, pl[g], vh4[0], vh4[1]);
                    mma16816(o1, ph[g], vh4[2], vh4[3]);
                    mma16816(o1, ph[g], vl4[2], vl4[3]);
                    mma16816(o1, pl[g], vh4[2], vh4[3]);
                }
            }
        }
        stq = stq == 2 ? 0 : stq + 1;
        stw = stw == 2 ? 0 : stw + 1;
    }
#undef AISSUE

    l0 += __shfl_xor_sync(0xffffffff, l0, 1);
    l0 += __shfl_xor_sync(0xffffffff, l0, 2);
    l1 += __shfl_xor_sync(0xffffffff, l1, 1);
    l1 += __shfl_xor_sync(0xffffffff, l1, 2);
    const float inv0 = 1.f / l0, inv1 = 1.f / l1;

    const int r = lane >> 2, c2 = (lane & 3) * 2;
    const size_t ob0 = ((size_t)bb * SS + wr0 + r) * DD + h * DH;
    const size_t ob1 = ((size_t)bb * SS + wr0 + r + 8) * DD + h * DH;
#pragma unroll
    for (int n8 = 0; n8 < 8; ++n8) {
        const int col = n8 * 8 + c2;
        uint32_t hi, lo;
        split2(O[n8][0] * inv0, O[n8][1] * inv0, hi, lo);
        *(uint32_t*)(oh_g + ob0 + col) = hi;
        *(uint32_t*)(ol_g + ob0 + col) = lo;
        split2(O[n8][2] * inv1, O[n8][3] * inv1, hi, lo);
        *(uint32_t*)(oh_g + ob1 + col) = hi;
        *(uint32_t*)(ol_g + ob1 + col) = lo;
    }
}

// ---------------------------------------------------------------------------
extern "C" void kernel_launch(void* const* d_in, const int* in_sizes, int n_in,
                              void* d_out, int out_size) {
    const float* queries = (const float*)d_in[0];
    const float* keys    = (const float*)d_in[1];
    const float* values  = (const float*)d_in[2];
    const float* W_Q = (const float*)d_in[3];
    const float* b_Q = (const float*)d_in[4];
    const float* W_K = (const float*)d_in[5];
    const float* b_K = (const float*)d_in[6];
    const float* W_V = (const float*)d_in[7];
    const float* b_V = (const float*)d_in[8];
    const float* W_O = (const float*)d_in[9];
    const float* b_O = (const float*)d_in[10];
    float* out = (float*)d_out;

    __nv_bfloat16 *qh, *ql, *kh, *kl, *vh, *vl;
    cudaGetSymbolAddress((void**)&qh, g_qh); cudaGetSymbolAddress((void**)&ql, g_ql);
    cudaGetSymbolAddress((void**)&kh, g_kh); cudaGetSymbolAddress((void**)&kl, g_kl);
    cudaGetSymbolAddress((void**)&vh, g_vh); cudaGetSymbolAddress((void**)&vl, g_vl);

    __nv_bfloat16 *aqh, *aql, *akh, *akl, *avh, *avl, *ath, *atl;
    __nv_bfloat16 *wqh, *wql, *wkh, *wkl, *wvh, *wvl, *woh, *wol;
    cudaGetSymbolAddress((void**)&aqh, g_aq_h); cudaGetSymbolAddress((void**)&aql, g_aq_l);
    cudaGetSymbolAddress((void**)&akh, g_ak_h); cudaGetSymbolAddress((void**)&akl, g_ak_l);
    cudaGetSymbolAddress((void**)&avh, g_av_h); cudaGetSymbolAddress((void**)&avl, g_av_l);
    cudaGetSymbolAddress((void**)&ath, g_at_h); cudaGetSymbolAddress((void**)&atl, g_at_l);
    cudaGetSymbolAddress((void**)&wqh, g_wq_h); cudaGetSymbolAddress((void**)&wql, g_wq_l);
    cudaGetSymbolAddress((void**)&wkh, g_wk_h); cudaGetSymbolAddress((void**)&wkl, g_wk_l);
    cudaGetSymbolAddress((void**)&wvh, g_wv_h); cudaGetSymbolAddress((void**)&wvl, g_wv_l);
    cudaGetSymbolAddress((void**)&woh, g_wo_h); cudaGetSymbolAddress((void**)&wol, g_wo_l);

    static bool attr_set = false;
    if (!attr_set) {
        cudaFuncSetAttribute(gemm_mma<0>, cudaFuncAttributeMaxDynamicSharedMemorySize, GSM_TOTAL);
        cudaFuncSetAttribute(gemm_mma<1>, cudaFuncAttributeMaxDynamicSharedMemorySize, GSM_TOTAL);
        cudaFuncSetAttribute(attn_mma, cudaFuncAttributeMaxDynamicSharedMemorySize, ATT_SMEM);
        attr_set = true;
    }

    const int nAct4 = MM * DD / 4;
    const int nW4   = DD * DD / 4;
    {
        dim3 g((nAct4 + 255) / 256, 3);
        cvt_split4<<<g, 256>>>(queries, aqh, aql, keys, akh, akl,
                               values, avh, avl, nullptr, nullptr, nullptr, nAct4);
    }
    {
        dim3 g((nW4 + 255) / 256, 4);
        cvt_split4<<<g, 256>>>(W_Q, wqh, wql, W_K, wkh, wkl,
                               W_V, wvh, wvl, W_O, woh, wol, nW4);
    }

    const float qscale = 1.0f / 8.0f;   // 1/sqrt(64)
    dim3 ggrid(MM / 128, DD / 128);     // 32 x 8

    gemm_mma<0><<<ggrid, 256, GSM_TOTAL>>>(aqh, aql, wqh, wql, b_Q, nullptr, qh, ql, qscale);
    gemm_mma<0><<<ggrid, 256, GSM_TOTAL>>>(akh, akl, wkh, wkl, b_K, nullptr, kh, kl, 1.0f);
    gemm_mma<0><<<ggrid, 256, GSM_TOTAL>>>(avh, avl, wvh, wvl, b_V, nullptr, vh, vl, 1.0f);

    dim3 agrid(SS / 128, HH, BB);       // 16 x 16 x 2
    attn_mma<<<agrid, 256, ATT_SMEM>>>(qh, ql, kh, kl, vh, vl, ath, atl);

    gemm_mma<1><<<ggrid, 256, GSM_TOTAL>>>(ath, atl, woh, wol, b_O, out, nullptr, nullptr, 1.0f);
}

// round 6
// speedup vs baseline: 4.1347x; 1.0788x over previous
#include <cuda_runtime.h>
#include <cuda_bf16.h>
#include <math.h>
#include <stdint.h>

// Problem constants
#define BB 2
#define SS 2048
#define DD 1024
#define HH 16
#define DH 64
#define MM (BB * SS)   // 4096

// ---------------------------------------------------------------------------
// Scratch (device globals; allocation APIs are forbidden)
// ---------------------------------------------------------------------------
__device__ __nv_bfloat16 g_qh[MM * DD], g_ql[MM * DD];
__device__ __nv_bfloat16 g_kh[MM * DD], g_kl[MM * DD];
__device__ __nv_bfloat16 g_vh[MM * DD], g_vl[MM * DD];

__device__ __nv_bfloat16 g_aq_h[MM * DD], g_aq_l[MM * DD];
__device__ __nv_bfloat16 g_ak_h[MM * DD], g_ak_l[MM * DD];
__device__ __nv_bfloat16 g_av_h[MM * DD], g_av_l[MM * DD];
__device__ __nv_bfloat16 g_at_h[MM * DD], g_at_l[MM * DD];
__device__ __nv_bfloat16 g_wq_h[DD * DD], g_wq_l[DD * DD];
__device__ __nv_bfloat16 g_wk_h[DD * DD], g_wk_l[DD * DD];
__device__ __nv_bfloat16 g_wv_h[DD * DD], g_wv_l[DD * DD];
__device__ __nv_bfloat16 g_wo_h[DD * DD], g_wo_l[DD * DD];

// ---------------------------------------------------------------------------
// PTX helpers (non-'a'-gated: mma.sync / ldmatrix / cp.async only)
// ---------------------------------------------------------------------------
__device__ __forceinline__ uint32_t smem_u32(const void* p) {
    uint32_t a;
    asm("{ .reg .u64 t; cvta.to.shared.u64 t, %1; cvt.u32.u64 %0, t; }"
        : "=r"(a) : "l"(p));
    return a;
}

__device__ __forceinline__ void cpa16(uint32_t s, const void* g) {
    asm volatile("cp.async.cg.shared.global [%0], [%1], 16;"
                 :: "r"(s), "l"(g) : "memory");
}

__device__ __forceinline__ void ldsm4(uint32_t* r, uint32_t a) {
    asm volatile("ldmatrix.sync.aligned.m8n8.x4.shared.b16 {%0,%1,%2,%3}, [%4];"
                 : "=r"(r[0]), "=r"(r[1]), "=r"(r[2]), "=r"(r[3]) : "r"(a));
}

__device__ __forceinline__ void ldsm4t(uint32_t* r, uint32_t a) {
    asm volatile("ldmatrix.sync.aligned.m8n8.x4.trans.shared.b16 {%0,%1,%2,%3}, [%4];"
                 : "=r"(r[0]), "=r"(r[1]), "=r"(r[2]), "=r"(r[3]) : "r"(a));
}

__device__ __forceinline__ void mma16816(float* d, const uint32_t* a,
                                         uint32_t b0, uint32_t b1) {
    asm volatile(
        "mma.sync.aligned.m16n8k16.row.col.f32.bf16.bf16.f32 "
        "{%0,%1,%2,%3}, {%4,%5,%6,%7}, {%8,%9}, {%0,%1,%2,%3};"
        : "+f"(d[0]), "+f"(d[1]), "+f"(d[2]), "+f"(d[3])
        : "r"(a[0]), "r"(a[1]), "r"(a[2]), "r"(a[3]), "r"(b0), "r"(b1));
}

__device__ __forceinline__ float ex2(float x) {
    float r;
    asm("ex2.approx.ftz.f32 %0, %1;" : "=f"(r) : "f"(x));
    return r;
}

// Cheap split: hi = truncate-to-bf16 (exact), lo = rn_bf16(x - hi).
// hi pack via PRMT, lo pack via single cvt.rn.bf16x2. 6 ops per 2 values.
__device__ __forceinline__ void split2t(float a, float b, uint32_t& hi, uint32_t& lo) {
    const uint32_t ua = __float_as_uint(a), ub = __float_as_uint(b);
    asm("prmt.b32 %0, %1, %2, 0x7632;" : "=r"(hi) : "r"(ua), "r"(ub));
    const float la = a - __uint_as_float(ua & 0xFFFF0000u);
    const float lb = b - __uint_as_float(ub & 0xFFFF0000u);
    asm("cvt.rn.bf16x2.f32 %0, %1, %2;" : "=r"(lo) : "f"(lb), "f"(la));
}

// ---------------------------------------------------------------------------
// fp32 -> (hi, lo) split; one launch for all 7 tensors (grid.y selects).
// ---------------------------------------------------------------------------
struct CvtP {
    const float* x[7];
    __nv_bfloat16* hi[7];
    __nv_bfloat16* lo[7];
    int n4[7];
};

__global__ __launch_bounds__(256)
void cvt_split7(CvtP p) {
    const int sel = blockIdx.y;
    const int i = blockIdx.x * 256 + threadIdx.x;
    if (i >= p.n4[sel]) return;
    float4 v = ((const float4*)p.x[sel])[i];
    uint2 h, l;
    split2t(v.x, v.y, h.x, l.x);
    split2t(v.z, v.w, h.y, l.y);
    ((uint2*)p.hi[sel])[i] = h;
    ((uint2*)p.lo[sel])[i] = l;
}

// ---------------------------------------------------------------------------
// Split-bf16 NT GEMM, 3-stage cp.async pipeline, one __syncthreads per k-tile.
// Tile 128x128x32, 256 threads (8 warps 4x2), warp tile 32x64.
// MODE 0: grid.z in {0,1,2} selects (A,W,bias,out) set; split-bf16 out (B,H,S,DH).
// MODE 1: z=0; fp32 out row-major (M,N).
// ---------------------------------------------------------------------------
#define BKT 32
#define STG_BYTES 32768
#define OFF_AH 0
#define OFF_AL 8192
#define OFF_BH 16384
#define OFF_BL 24576
#define GSM_TOTAL (3 * STG_BYTES)   // 96 KB

struct GemmP {
    const __nv_bfloat16 *Ah[3], *Al[3], *Bh[3], *Bl[3];
    const float* bias[3];
    float* C;                         // MODE 1
    __nv_bfloat16 *Ch[3], *Cl[3];     // MODE 0
    float scale[3];
};

template <int MODE>
__global__ __launch_bounds__(256, 2)
void gemm_mma(GemmP p) {
    extern __shared__ char smc[];
    const uint32_t sb = smem_u32(smc);
    const int z = blockIdx.z;
    const __nv_bfloat16* __restrict__ Ah = p.Ah[z];
    const __nv_bfloat16* __restrict__ Al = p.Al[z];
    const __nv_bfloat16* __restrict__ Bh = p.Bh[z];
    const __nv_bfloat16* __restrict__ Bl = p.Bl[z];
    const float* __restrict__ bias = p.bias[z];
    const float scale = p.scale[z];

    const int tid = threadIdx.x;
    const int lane = tid & 31, wid = tid >> 5;
    const int wm = (wid & 3) * 32;
    const int wn = (wid >> 2) * 64;
    const int m0 = blockIdx.x * 128, n0 = blockIdx.y * 128;

    const int lr = tid >> 2;
    const int lc = tid & 3;

    float d[2][8][4] = {};

#define ISSUE_STAGE(it, sbase)                                                   \
    {                                                                            \
        const int k0 = (it) * BKT;                                               \
        _Pragma("unroll")                                                        \
        for (int rep = 0; rep < 2; ++rep) {                                      \
            const int row = lr + rep * 64;                                       \
            const uint32_t soff = row * 64 + ((lc ^ ((row >> 1) & 3)) << 4);     \
            const size_t ga = (size_t)(m0 + row) * DD + k0 + lc * 8;             \
            const size_t gb = (size_t)(n0 + row) * DD + k0 + lc * 8;             \
            cpa16(sb + (sbase) + OFF_AH + soff, Ah + ga);                        \
            cpa16(sb + (sbase) + OFF_AL + soff, Al + ga);                        \
            cpa16(sb + (sbase) + OFF_BH + soff, Bh + gb);                        \
            cpa16(sb + (sbase) + OFF_BL + soff, Bl + gb);                        \
        }                                                                        \
    }

    ISSUE_STAGE(0, 0);
    asm volatile("cp.async.commit_group;" ::: "memory");
    ISSUE_STAGE(1, STG_BYTES);
    asm volatile("cp.async.commit_group;" ::: "memory");

    int stq = 0;
    int stw = 2;
    for (int it = 0; it < DD / BKT; ++it) {
        asm volatile("cp.async.wait_group 1;" ::: "memory");
        __syncthreads();
        if (it + 2 < DD / BKT) {
            ISSUE_STAGE(it + 2, stw * STG_BYTES);
        }
        asm volatile("cp.async.commit_group;" ::: "memory");

        const uint32_t st = sb + stq * STG_BYTES;
#pragma unroll
        for (int ks = 0; ks < 2; ++ks) {
            uint32_t ah[2][4], al[2][4], bh[4][4], bl[4][4];
#pragma unroll
            for (int mi = 0; mi < 2; ++mi) {
                const int row = wm + mi * 16 + (lane & 15);
                const int ch = ks * 2 + (lane >> 4);
                const uint32_t ad = st + row * 64 + ((ch ^ ((row >> 1) & 3)) << 4);
                ldsm4(ah[mi], ad + OFF_AH);
                ldsm4(al[mi], ad + OFF_AL);
            }
#pragma unroll
            for (int ng = 0; ng < 4; ++ng) {
                const int row = wn + ng * 16 + (lane & 7) + ((lane >> 4) << 3);
                const int ch = ks * 2 + ((lane >> 3) & 1);
                const uint32_t bd = st + row * 64 + ((ch ^ ((row >> 1) & 3)) << 4);
                ldsm4(bh[ng], bd + OFF_BH);
                ldsm4(bl[ng], bd + OFF_BL);
            }
#pragma unroll
            for (int mi = 0; mi < 2; ++mi) {
#pragma unroll
                for (int n8 = 0; n8 < 8; ++n8) {
                    const int ng = n8 >> 1, hf = n8 & 1;
                    float* dd = d[mi][n8];
                    mma16816(dd, ah[mi], bh[ng][hf * 2], bh[ng][hf * 2 + 1]);
                    mma16816(dd, ah[mi], bl[ng][hf * 2], bl[ng][hf * 2 + 1]);
                    mma16816(dd, al[mi], bh[ng][hf * 2], bh[ng][hf * 2 + 1]);
                }
            }
        }
        stq = stq == 2 ? 0 : stq + 1;
        stw = stw == 2 ? 0 : stw + 1;
    }
#undef ISSUE_STAGE

    const int row = lane >> 2, colp = (lane & 3) * 2;
#pragma unroll
    for (int mi = 0; mi < 2; ++mi) {
#pragma unroll
        for (int n8 = 0; n8 < 8; ++n8) {
            const float* dd = d[mi][n8];
            const int n = n0 + wn + n8 * 8 + colp;
            const float2 b2 = *(const float2*)(bias + n);
#pragma unroll
            for (int rh = 0; rh < 2; ++rh) {
                const int m = m0 + wm + mi * 16 + row + rh * 8;
                float rx = (dd[rh * 2 + 0] + b2.x) * scale;
                float ry = (dd[rh * 2 + 1] + b2.y) * scale;
                if (MODE == 0) {
                    const int bb = m >> 11, s = m & (SS - 1);
                    const int h = n >> 6, dh = n & (DH - 1);
                    const size_t idx = ((size_t)(bb * HH + h) * SS + s) * DH + dh;
                    uint32_t hi, lo;
                    split2t(rx, ry, hi, lo);
                    *(uint32_t*)(p.Ch[z] + idx) = hi;
                    *(uint32_t*)(p.Cl[z] + idx) = lo;
                } else {
                    float2 r2 = make_float2(rx, ry);
                    *(float2*)(p.C + (size_t)m * DD + n) = r2;
                }
            }
        }
    }
}

// ---------------------------------------------------------------------------
// Flash attention via mma.sync, split-bf16 QK^T and PV.
// Scores are pre-scaled by log2(e)/8 (folded into Q projection) -> ex2 softmax.
// 3-stage cp.async pipeline, one sync per 64-key tile.
// ---------------------------------------------------------------------------
#define ATT_STG 32768
#define ATT_SMEM (3 * ATT_STG)   // 96 KB

__global__ __launch_bounds__(256)
void attn_mma(const __nv_bfloat16* __restrict__ qh_g, const __nv_bfloat16* __restrict__ ql_g,
              const __nv_bfloat16* __restrict__ kh_g, const __nv_bfloat16* __restrict__ kl_g,
              const __nv_bfloat16* __restrict__ vh_g, const __nv_bfloat16* __restrict__ vl_g,
              __nv_bfloat16* __restrict__ oh_g, __nv_bfloat16* __restrict__ ol_g) {
    extern __shared__ char smc[];
    const uint32_t sb = smem_u32(smc);
    const int tid = threadIdx.x, lane = tid & 31, w = tid >> 5;
    const int qt = gridDim.x - 1 - (int)blockIdx.x;   // heavy blocks first
    const int h = blockIdx.y, bb = blockIdx.z;
    const int q0 = qt * 128;
    const size_t hb = (size_t)(bb * HH + h) * SS * DH;
    const int wr0 = q0 + w * 16;
    const int nkt = qt * 2 + 2;

    uint32_t qfh[4][4], qfl[4][4];
    {
        const int r = lane >> 2, c2 = (lane & 3) * 2;
#pragma unroll
        for (int f = 0; f < 4; ++f) {
#pragma unroll
            for (int idx = 0; idx < 4; ++idx) {
                const int rr = r + (idx & 1) * 8;
                const int kk = f * 16 + c2 + (idx >> 1) * 8;
                const size_t off = hb + (size_t)(wr0 + rr) * DH + kk;
                qfh[f][idx] = *(const uint32_t*)(qh_g + off);
                qfl[f][idx] = *(const uint32_t*)(ql_g + off);
            }
        }
    }

    float O[8][4] = {};
    float m0v = -1e30f, m1v = -1e30f, l0 = 0.f, l1 = 0.f;

    const __nv_bfloat16* srcs[4] = { kh_g + hb, kl_g + hb, vh_g + hb, vl_g + hb };

#define AISSUE(kt, sbase)                                                        \
    {                                                                            \
        const int kb_ = (kt) * 64;                                               \
        _Pragma("unroll")                                                        \
        for (int t = 0; t < 8; ++t) {                                            \
            const int c = tid + t * 256;                                         \
            const int arr = c >> 9;                                              \
            const int row = (c >> 3) & 63;                                       \
            const int ch = c & 7;                                                \
            const uint32_t dst = sb + (sbase) + arr * 8192 + row * 128           \
                                 + ((ch ^ (row & 7)) << 4);                      \
            cpa16(dst, srcs[arr] + (size_t)(kb_ + row) * DH + ch * 8);           \
        }                                                                        \
    }

    AISSUE(0, 0);
    asm volatile("cp.async.commit_group;" ::: "memory");
    AISSUE(1, ATT_STG);
    asm volatile("cp.async.commit_group;" ::: "memory");

    int stq = 0, stw = 2;
    for (int it = 0; it < nkt; ++it) {
        asm volatile("cp.async.wait_group 1;" ::: "memory");
        __syncthreads();
        if (it + 2 < nkt) {
            AISSUE(it + 2, stw * ATT_STG);
        }
        asm volatile("cp.async.commit_group;" ::: "memory");

        const int kb = it * 64;
        if (kb <= wr0 + 15) {
            const uint32_t st = sb + stq * ATT_STG;
            float s[8][4] = {};

            const int srow_b = (lane & 7) + ((lane >> 4) << 3);
            const int sch_b = (lane >> 3) & 1;
#pragma unroll
            for (int f = 0; f < 4; ++f) {
#pragma unroll
                for (int ng = 0; ng < 4; ++ng) {
                    const int row = ng * 16 + srow_b;
                    const int ch = f * 2 + sch_b;
                    const uint32_t ad = st + row * 128 + ((ch ^ (row & 7)) << 4);
                    uint32_t kh4[4], kl4[4];
                    ldsm4(kh4, ad);
                    ldsm4(kl4, ad + 8192);
#pragma unroll
                    for (int hf = 0; hf < 2; ++hf) {
                        float* ss = s[ng * 2 + hf];
                        mma16816(ss, qfh[f], kh4[hf * 2], kh4[hf * 2 + 1]);
                        mma16816(ss, qfh[f], kl4[hf * 2], kl4[hf * 2 + 1]);
                        mma16816(ss, qfl[f], kh4[hf * 2], kh4[hf * 2 + 1]);
                    }
                }
            }

            if (kb + 63 > wr0) {
                const int r0g = wr0 + (lane >> 2), r1g = r0g + 8;
#pragma unroll
                for (int n8 = 0; n8 < 8; ++n8) {
                    const int c0 = kb + n8 * 8 + (lane & 3) * 2;
                    if (c0 > r0g)     s[n8][0] = -1e30f;
                    if (c0 + 1 > r0g) s[n8][1] = -1e30f;
                    if (c0 > r1g)     s[n8][2] = -1e30f;
                    if (c0 + 1 > r1g) s[n8][3] = -1e30f;
                }
            }

            float t0 = -1e30f, t1 = -1e30f;
#pragma unroll
            for (int n8 = 0; n8 < 8; ++n8) {
                t0 = fmaxf(t0, fmaxf(s[n8][0], s[n8][1]));
                t1 = fmaxf(t1, fmaxf(s[n8][2], s[n8][3]));
            }
            t0 = fmaxf(t0, __shfl_xor_sync(0xffffffff, t0, 1));
            t0 = fmaxf(t0, __shfl_xor_sync(0xffffffff, t0, 2));
            t1 = fmaxf(t1, __shfl_xor_sync(0xffffffff, t1, 1));
            t1 = fmaxf(t1, __shfl_xor_sync(0xffffffff, t1, 2));

            const float mn0 = fmaxf(m0v, t0), mn1 = fmaxf(m1v, t1);
            const float cr0 = ex2(m0v - mn0), cr1 = ex2(m1v - mn1);
            m0v = mn0; m1v = mn1;
            l0 *= cr0; l1 *= cr1;
#pragma unroll
            for (int n8 = 0; n8 < 8; ++n8) {
                O[n8][0] *= cr0; O[n8][1] *= cr0;
                O[n8][2] *= cr1; O[n8][3] *= cr1;
            }

            uint32_t ph[4][4], pl[4][4];
#pragma unroll
            for (int g = 0; g < 4; ++g) {
#pragma unroll
                for (int hf = 0; hf < 2; ++hf) {
                    const float* ss = s[g * 2 + hf];
                    const float p0 = ex2(ss[0] - m0v);
                    const float p1 = ex2(ss[1] - m0v);
                    const float p2 = ex2(ss[2] - m1v);
                    const float p3 = ex2(ss[3] - m1v);
                    l0 += p0 + p1;
                    l1 += p2 + p3;
                    split2t(p0, p1, ph[g][hf * 2], pl[g][hf * 2]);
                    split2t(p2, p3, ph[g][hf * 2 + 1], pl[g][hf * 2 + 1]);
                }
            }

            const int vrow_b = (lane & 7) + ((lane >> 3) & 1) * 8;
            const int vch_b = lane >> 4;
#pragma unroll
            for (int g = 0; g < 4; ++g) {
                const int row = g * 16 + vrow_b;
#pragma unroll
                for (int no = 0; no < 4; ++no) {
                    const int ch = no * 2 + vch_b;
                    const uint32_t ad = st + 16384 + row * 128 + ((ch ^ (row & 7)) << 4);
                    uint32_t vh4[4], vl4[4];
                    ldsm4t(vh4, ad);
                    ldsm4t(vl4, ad + 8192);
                    float* o0 = O[no * 2];
                    float* o1 = O[no * 2 + 1];
                    mma16816(o0, ph[g], vh4[0], vh4[1]);
                    mma16816(o0, ph[g], vl4[0], vl4[1]);
                    mma16816(o0, pl[g], vh4[0], vh4[1]);
                    mma16816(o1, ph[g], vh4[2], vh4[3]);
                    mma16816(o1, ph[g], vl4[2], vl4[3]);
                    mma16816(o1, pl[g], vh4[2], vh4[3]);
                }
            }
        }
        stq = stq == 2 ? 0 : stq + 1;
        stw = stw == 2 ? 0 : stw + 1;
    }
#undef AISSUE

    l0 += __shfl_xor_sync(0xffffffff, l0, 1);
    l0 += __shfl_xor_sync(0xffffffff, l0, 2);
    l1 += __shfl_xor_sync(0xffffffff, l1, 1);
    l1 += __shfl_xor_sync(0xffffffff, l1, 2);
    const float inv0 = 1.f / l0, inv1 = 1.f / l1;

    const int r = lane >> 2, c2 = (lane & 3) * 2;
    const size_t ob0 = ((size_t)bb * SS + wr0 + r) * DD + h * DH;
    const size_t ob1 = ((size_t)bb * SS + wr0 + r + 8) * DD + h * DH;
#pragma unroll
    for (int n8 = 0; n8 < 8; ++n8) {
        const int col = n8 * 8 + c2;
        uint32_t hi, lo;
        split2t(O[n8][0] * inv0, O[n8][1] * inv0, hi, lo);
        *(uint32_t*)(oh_g + ob0 + col) = hi;
        *(uint32_t*)(ol_g + ob0 + col) = lo;
        split2t(O[n8][2] * inv1, O[n8][3] * inv1, hi, lo);
        *(uint32_t*)(oh_g + ob1 + col) = hi;
        *(uint32_t*)(ol_g + ob1 + col) = lo;
    }
}

// ---------------------------------------------------------------------------
extern "C" void kernel_launch(void* const* d_in, const int* in_sizes, int n_in,
                              void* d_out, int out_size) {
    const float* queries = (const float*)d_in[0];
    const float* keys    = (const float*)d_in[1];
    const float* values  = (const float*)d_in[2];
    const float* W_Q = (const float*)d_in[3];
    const float* b_Q = (const float*)d_in[4];
    const float* W_K = (const float*)d_in[5];
    const float* b_K = (const float*)d_in[6];
    const float* W_V = (const float*)d_in[7];
    const float* b_V = (const float*)d_in[8];
    const float* W_O = (const float*)d_in[9];
    const float* b_O = (const float*)d_in[10];
    float* out = (float*)d_out;

    __nv_bfloat16 *qh, *ql, *kh, *kl, *vh, *vl;
    cudaGetSymbolAddress((void**)&qh, g_qh); cudaGetSymbolAddress((void**)&ql, g_ql);
    cudaGetSymbolAddress((void**)&kh, g_kh); cudaGetSymbolAddress((void**)&kl, g_kl);
    cudaGetSymbolAddress((void**)&vh, g_vh); cudaGetSymbolAddress((void**)&vl, g_vl);

    __nv_bfloat16 *aqh, *aql, *akh, *akl, *avh, *avl, *ath, *atl;
    __nv_bfloat16 *wqh, *wql, *wkh, *wkl, *wvh, *wvl, *woh, *wol;
    cudaGetSymbolAddress((void**)&aqh, g_aq_h); cudaGetSymbolAddress((void**)&aql, g_aq_l);
    cudaGetSymbolAddress((void**)&akh, g_ak_h); cudaGetSymbolAddress((void**)&akl, g_ak_l);
    cudaGetSymbolAddress((void**)&avh, g_av_h); cudaGetSymbolAddress((void**)&avl, g_av_l);
    cudaGetSymbolAddress((void**)&ath, g_at_h); cudaGetSymbolAddress((void**)&atl, g_at_l);
    cudaGetSymbolAddress((void**)&wqh, g_wq_h); cudaGetSymbolAddress((void**)&wql, g_wq_l);
    cudaGetSymbolAddress((void**)&wkh, g_wk_h); cudaGetSymbolAddress((void**)&wkl, g_wk_l);
    cudaGetSymbolAddress((void**)&wvh, g_wv_h); cudaGetSymbolAddress((void**)&wvl, g_wv_l);
    cudaGetSymbolAddress((void**)&woh, g_wo_h); cudaGetSymbolAddress((void**)&wol, g_wo_l);

    static bool attr_set = false;
    if (!attr_set) {
        cudaFuncSetAttribute(gemm_mma<0>, cudaFuncAttributeMaxDynamicSharedMemorySize, GSM_TOTAL);
        cudaFuncSetAttribute(gemm_mma<1>, cudaFuncAttributeMaxDynamicSharedMemorySize, GSM_TOTAL);
        cudaFuncSetAttribute(attn_mma, cudaFuncAttributeMaxDynamicSharedMemorySize, ATT_SMEM);
        attr_set = true;
    }

    const int nAct4 = MM * DD / 4;
    const int nW4   = DD * DD / 4;

    // One conversion launch for all 7 fp32 tensors
    {
        CvtP cp;
        cp.x[0] = queries; cp.hi[0] = aqh; cp.lo[0] = aql; cp.n4[0] = nAct4;
        cp.x[1] = keys;    cp.hi[1] = akh; cp.lo[1] = akl; cp.n4[1] = nAct4;
        cp.x[2] = values;  cp.hi[2] = avh; cp.lo[2] = avl; cp.n4[2] = nAct4;
        cp.x[3] = W_Q;     cp.hi[3] = wqh; cp.lo[3] = wql; cp.n4[3] = nW4;
        cp.x[4] = W_K;     cp.hi[4] = wkh; cp.lo[4] = wkl; cp.n4[4] = nW4;
        cp.x[5] = W_V;     cp.hi[5] = wvh; cp.lo[5] = wvl; cp.n4[5] = nW4;
        cp.x[6] = W_O;     cp.hi[6] = woh; cp.lo[6] = wol; cp.n4[6] = nW4;
        dim3 g((nAct4 + 255) / 256, 7);
        cvt_split7<<<g, 256>>>(cp);
    }

    // Q pre-scale includes log2(e) for ex2-based softmax
    const float qscale = 0.125f * 1.4426950408889634f;

    // Merged Q/K/V projection GEMMs: grid.z selects the set
    {
        GemmP gp = {};
        gp.Ah[0] = aqh; gp.Al[0] = aql; gp.Bh[0] = wqh; gp.Bl[0] = wql;
        gp.Ah[1] = akh; gp.Al[1] = akl; gp.Bh[1] = wkh; gp.Bl[1] = wkl;
        gp.Ah[2] = avh; gp.Al[2] = avl; gp.Bh[2] = wvh; gp.Bl[2] = wvl;
        gp.bias[0] = b_Q; gp.bias[1] = b_K; gp.bias[2] = b_V;
        gp.Ch[0] = qh; gp.Cl[0] = ql;
        gp.Ch[1] = kh; gp.Cl[1] = kl;
        gp.Ch[2] = vh; gp.Cl[2] = vl;
        gp.scale[0] = qscale; gp.scale[1] = 1.0f; gp.scale[2] = 1.0f;
        gp.C = nullptr;
        dim3 g(MM / 128, DD / 128, 3);   // 32 x 8 x 3 = 768 CTAs
        gemm_mma<0><<<g, 256, GSM_TOTAL>>>(gp);
    }

    dim3 agrid(SS / 128, HH, BB);       // 16 x 16 x 2
    attn_mma<<<agrid, 256, ATT_SMEM>>>(qh, ql, kh, kl, vh, vl, ath, atl);

    // Output projection
    {
        GemmP gp = {};
        gp.Ah[0] = ath; gp.Al[0] = atl; gp.Bh[0] = woh; gp.Bl[0] = wol;
        gp.bias[0] = b_O;
        gp.scale[0] = 1.0f;
        gp.C = out;
        dim3 g(MM / 128, DD / 128, 1);
        gemm_mma<1><<<g, 256, GSM_TOTAL>>>(gp);
    }
}

// round 7
// speedup vs baseline: 4.3960x; 1.0632x over previous
#include <cuda_runtime.h>
#include <cuda_bf16.h>
#include <math.h>
#include <stdint.h>

// Problem constants
#define BB 2
#define SS 2048
#define DD 1024
#define HH 16
#define DH 64
#define MM (BB * SS)   // 4096

// ---------------------------------------------------------------------------
// Scratch (device globals; allocation APIs are forbidden)
// ---------------------------------------------------------------------------
__device__ __nv_bfloat16 g_qh[MM * DD], g_ql[MM * DD];
__device__ __nv_bfloat16 g_kh[MM * DD], g_kl[MM * DD];
__device__ __nv_bfloat16 g_vh[MM * DD], g_vl[MM * DD];

__device__ __nv_bfloat16 g_aq_h[MM * DD], g_aq_l[MM * DD];
__device__ __nv_bfloat16 g_ak_h[MM * DD], g_ak_l[MM * DD];
__device__ __nv_bfloat16 g_av_h[MM * DD], g_av_l[MM * DD];
__device__ __nv_bfloat16 g_at_h[MM * DD], g_at_l[MM * DD];
__device__ __nv_bfloat16 g_wq_h[DD * DD], g_wq_l[DD * DD];
__device__ __nv_bfloat16 g_wk_h[DD * DD], g_wk_l[DD * DD];
__device__ __nv_bfloat16 g_wv_h[DD * DD], g_wv_l[DD * DD];
__device__ __nv_bfloat16 g_wo_h[DD * DD], g_wo_l[DD * DD];

// ---------------------------------------------------------------------------
// PTX helpers (non-'a'-gated: mma.sync / ldmatrix / cp.async only)
// ---------------------------------------------------------------------------
__device__ __forceinline__ uint32_t smem_u32(const void* p) {
    uint32_t a;
    asm("{ .reg .u64 t; cvta.to.shared.u64 t, %1; cvt.u32.u64 %0, t; }"
        : "=r"(a) : "l"(p));
    return a;
}

__device__ __forceinline__ void cpa16(uint32_t s, const void* g) {
    asm volatile("cp.async.cg.shared.global [%0], [%1], 16;"
                 :: "r"(s), "l"(g) : "memory");
}

__device__ __forceinline__ void ldsm4(uint32_t* r, uint32_t a) {
    asm volatile("ldmatrix.sync.aligned.m8n8.x4.shared.b16 {%0,%1,%2,%3}, [%4];"
                 : "=r"(r[0]), "=r"(r[1]), "=r"(r[2]), "=r"(r[3]) : "r"(a));
}

__device__ __forceinline__ void ldsm4t(uint32_t* r, uint32_t a) {
    asm volatile("ldmatrix.sync.aligned.m8n8.x4.trans.shared.b16 {%0,%1,%2,%3}, [%4];"
                 : "=r"(r[0]), "=r"(r[1]), "=r"(r[2]), "=r"(r[3]) : "r"(a));
}

__device__ __forceinline__ void mma16816(float* d, const uint32_t* a,
                                         uint32_t b0, uint32_t b1) {
    asm volatile(
        "mma.sync.aligned.m16n8k16.row.col.f32.bf16.bf16.f32 "
        "{%0,%1,%2,%3}, {%4,%5,%6,%7}, {%8,%9}, {%0,%1,%2,%3};"
        : "+f"(d[0]), "+f"(d[1]), "+f"(d[2]), "+f"(d[3])
        : "r"(a[0]), "r"(a[1]), "r"(a[2]), "r"(a[3]), "r"(b0), "r"(b1));
}

__device__ __forceinline__ float ex2(float x) {
    float r;
    asm("ex2.approx.ftz.f32 %0, %1;" : "=f"(r) : "f"(x));
    return r;
}

// Cheap split: hi = truncate-to-bf16 (exact), lo = rn_bf16(x - hi).
__device__ __forceinline__ void split2t(float a, float b, uint32_t& hi, uint32_t& lo) {
    const uint32_t ua = __float_as_uint(a), ub = __float_as_uint(b);
    asm("prmt.b32 %0, %1, %2, 0x7632;" : "=r"(hi) : "r"(ua), "r"(ub));
    const float la = a - __uint_as_float(ua & 0xFFFF0000u);
    const float lb = b - __uint_as_float(ub & 0xFFFF0000u);
    asm("cvt.rn.bf16x2.f32 %0, %1, %2;" : "=r"(lo) : "f"(lb), "f"(la));
}

// ---------------------------------------------------------------------------
// fp32 -> (hi, lo) split; one launch for all 7 tensors (grid.y selects).
// ---------------------------------------------------------------------------
struct CvtP {
    const float* x[7];
    __nv_bfloat16* hi[7];
    __nv_bfloat16* lo[7];
    int n4[7];
};

__global__ __launch_bounds__(256)
void cvt_split7(CvtP p) {
    const int sel = blockIdx.y;
    const int i = blockIdx.x * 256 + threadIdx.x;
    if (i >= p.n4[sel]) return;
    float4 v = ((const float4*)p.x[sel])[i];
    uint2 h, l;
    split2t(v.x, v.y, h.x, l.x);
    split2t(v.z, v.w, h.y, l.y);
    ((uint2*)p.hi[sel])[i] = h;
    ((uint2*)p.lo[sel])[i] = l;
}

// ---------------------------------------------------------------------------
// Split-bf16 NT GEMM, 3-stage cp.async pipeline.
// Block tile 128x256x32, 256 threads (8 warps 2x4), warp tile 64x64.
// (warp-tile 64x64 halves smem bytes/MMA vs 32x64 -> crossbar no longer binds)
// cp.async for stage it+2 issued BETWEEN the two k16 compute halves.
// MODE 0: grid.z selects QKV set; split-bf16 out (B,H,S,DH).
// MODE 1: fp32 out row-major (M,N).
// ---------------------------------------------------------------------------
#define BKT 32
#define OFF_AH 0
#define OFF_AL 8192
#define OFF_BH 16384
#define OFF_BL 32768
#define STG_BYTES 49152
#define GSM_TOTAL (3 * STG_BYTES)   // 144 KB, occ 1

struct GemmP {
    const __nv_bfloat16 *Ah[3], *Al[3], *Bh[3], *Bl[3];
    const float* bias[3];
    float* C;                         // MODE 1
    __nv_bfloat16 *Ch[3], *Cl[3];     // MODE 0
    float scale[3];
};

template <int MODE>
__global__ __launch_bounds__(256)
void gemm_mma(GemmP p) {
    extern __shared__ char smc[];
    const uint32_t sb = smem_u32(smc);
    const int z = blockIdx.z;
    const __nv_bfloat16* __restrict__ Ah = p.Ah[z];
    const __nv_bfloat16* __restrict__ Al = p.Al[z];
    const __nv_bfloat16* __restrict__ Bh = p.Bh[z];
    const __nv_bfloat16* __restrict__ Bl = p.Bl[z];
    const float* __restrict__ bias = p.bias[z];
    const float scale = p.scale[z];

    const int tid = threadIdx.x;
    const int lane = tid & 31, wid = tid >> 5;
    const int wm = (wid & 1) * 64;      // 2 m-warps
    const int wn = (wid >> 1) * 64;     // 4 n-warps
    const int m0 = blockIdx.x * 128, n0 = blockIdx.y * 256;

    const int lr = tid >> 2;            // 0..63
    const int lc = tid & 3;             // 16B chunk

    float d[4][8][4] = {};

#define ISSUE_STAGE(it, sbase)                                                   \
    {                                                                            \
        const int k0 = (it) * BKT;                                               \
        _Pragma("unroll")                                                        \
        for (int rep = 0; rep < 2; ++rep) {                                      \
            const int row = lr + rep * 64;                                       \
            const uint32_t soff = row * 64 + ((lc ^ ((row >> 1) & 3)) << 4);     \
            const size_t ga = (size_t)(m0 + row) * DD + k0 + lc * 8;             \
            cpa16(sb + (sbase) + OFF_AH + soff, Ah + ga);                        \
            cpa16(sb + (sbase) + OFF_AL + soff, Al + ga);                        \
        }                                                                        \
        _Pragma("unroll")                                                        \
        for (int rep = 0; rep < 4; ++rep) {                                      \
            const int row = lr + rep * 64;                                       \
            const uint32_t soff = row * 64 + ((lc ^ ((row >> 1) & 3)) << 4);     \
            const size_t gb = (size_t)(n0 + row) * DD + k0 + lc * 8;             \
            cpa16(sb + (sbase) + OFF_BH + soff, Bh + gb);                        \
            cpa16(sb + (sbase) + OFF_BL + soff, Bl + gb);                        \
        }                                                                        \
    }

#define COMPUTE_KS(ks)                                                           \
    {                                                                            \
        uint32_t ah[4][4], al[4][4], bh[4][4], bl[4][4];                         \
        _Pragma("unroll")                                                        \
        for (int mi = 0; mi < 4; ++mi) {                                         \
            const int row = wm + mi * 16 + (lane & 15);                          \
            const int ch = (ks) * 2 + (lane >> 4);                               \
            const uint32_t ad = st + row * 64 + ((ch ^ ((row >> 1) & 3)) << 4);  \
            ldsm4(ah[mi], ad + OFF_AH);                                          \
            ldsm4(al[mi], ad + OFF_AL);                                          \
        }                                                                        \
        _Pragma("unroll")                                                        \
        for (int ng = 0; ng < 4; ++ng) {                                         \
            const int row = wn + ng * 16 + (lane & 7) + ((lane >> 4) << 3);      \
            const int ch = (ks) * 2 + ((lane >> 3) & 1);                         \
            const uint32_t bd = st + row * 64 + ((ch ^ ((row >> 1) & 3)) << 4);  \
            ldsm4(bh[ng], bd + OFF_BH);                                          \
            ldsm4(bl[ng], bd + OFF_BL);                                          \
        }                                                                        \
        _Pragma("unroll")                                                        \
        for (int mi = 0; mi < 4; ++mi) {                                         \
            _Pragma("unroll")                                                    \
            for (int n8 = 0; n8 < 8; ++n8) {                                     \
                const int ng = n8 >> 1, hf = n8 & 1;                             \
                float* dd = d[mi][n8];                                           \
                mma16816(dd, ah[mi], bh[ng][hf * 2], bh[ng][hf * 2 + 1]);        \
                mma16816(dd, ah[mi], bl[ng][hf * 2], bl[ng][hf * 2 + 1]);        \
                mma16816(dd, al[mi], bh[ng][hf * 2], bh[ng][hf * 2 + 1]);        \
            }                                                                    \
        }                                                                        \
    }

    ISSUE_STAGE(0, 0);
    asm volatile("cp.async.commit_group;" ::: "memory");
    ISSUE_STAGE(1, STG_BYTES);
    asm volatile("cp.async.commit_group;" ::: "memory");

    int stq = 0;
    int stw = 2;
    for (int it = 0; it < DD / BKT; ++it) {
        asm volatile("cp.async.wait_group 1;" ::: "memory");
        __syncthreads();
        const uint32_t st = sb + stq * STG_BYTES;

        COMPUTE_KS(0);
        // overlap next-stage load issue with tensor work
        if (it + 2 < DD / BKT) {
            ISSUE_STAGE(it + 2, stw * STG_BYTES);
        }
        asm volatile("cp.async.commit_group;" ::: "memory");
        COMPUTE_KS(1);

        stq = stq == 2 ? 0 : stq + 1;
        stw = stw == 2 ? 0 : stw + 1;
    }
#undef ISSUE_STAGE
#undef COMPUTE_KS

    const int row = lane >> 2, colp = (lane & 3) * 2;
#pragma unroll
    for (int mi = 0; mi < 4; ++mi) {
#pragma unroll
        for (int n8 = 0; n8 < 8; ++n8) {
            const float* dd = d[mi][n8];
            const int n = n0 + wn + n8 * 8 + colp;
            const float2 b2 = *(const float2*)(bias + n);
#pragma unroll
            for (int rh = 0; rh < 2; ++rh) {
                const int m = m0 + wm + mi * 16 + row + rh * 8;
                float rx = (dd[rh * 2 + 0] + b2.x) * scale;
                float ry = (dd[rh * 2 + 1] + b2.y) * scale;
                if (MODE == 0) {
                    const int bb = m >> 11, s = m & (SS - 1);
                    const int h = n >> 6, dh = n & (DH - 1);
                    const size_t idx = ((size_t)(bb * HH + h) * SS + s) * DH + dh;
                    uint32_t hi, lo;
                    split2t(rx, ry, hi, lo);
                    *(uint32_t*)(p.Ch[z] + idx) = hi;
                    *(uint32_t*)(p.Cl[z] + idx) = lo;
                } else {
                    float2 r2 = make_float2(rx, ry);
                    *(float2*)(p.C + (size_t)m * DD + n) = r2;
                }
            }
        }
    }
}

// ---------------------------------------------------------------------------
// Flash attention via mma.sync, split-bf16 QK^T and PV. ex2 softmax.
// 3-stage cp.async pipeline; next-stage issue sunk between QK^T and PV.
// ---------------------------------------------------------------------------
#define ATT_STG 32768
#define ATT_SMEM (3 * ATT_STG)   // 96 KB

__global__ __launch_bounds__(256)
void attn_mma(const __nv_bfloat16* __restrict__ qh_g, const __nv_bfloat16* __restrict__ ql_g,
              const __nv_bfloat16* __restrict__ kh_g, const __nv_bfloat16* __restrict__ kl_g,
              const __nv_bfloat16* __restrict__ vh_g, const __nv_bfloat16* __restrict__ vl_g,
              __nv_bfloat16* __restrict__ oh_g, __nv_bfloat16* __restrict__ ol_g) {
    extern __shared__ char smc[];
    const uint32_t sb = smem_u32(smc);
    const int tid = threadIdx.x, lane = tid & 31, w = tid >> 5;
    const int qt = gridDim.x - 1 - (int)blockIdx.x;   // heavy blocks first
    const int h = blockIdx.y, bb = blockIdx.z;
    const int q0 = qt * 128;
    const size_t hb = (size_t)(bb * HH + h) * SS * DH;
    const int wr0 = q0 + w * 16;
    const int nkt = qt * 2 + 2;

    uint32_t qfh[4][4], qfl[4][4];
    {
        const int r = lane >> 2, c2 = (lane & 3) * 2;
#pragma unroll
        for (int f = 0; f < 4; ++f) {
#pragma unroll
            for (int idx = 0; idx < 4; ++idx) {
                const int rr = r + (idx & 1) * 8;
                const int kk = f * 16 + c2 + (idx >> 1) * 8;
                const size_t off = hb + (size_t)(wr0 + rr) * DH + kk;
                qfh[f][idx] = *(const uint32_t*)(qh_g + off);
                qfl[f][idx] = *(const uint32_t*)(ql_g + off);
            }
        }
    }

    float O[8][4] = {};
    float m0v = -1e30f, m1v = -1e30f, l0 = 0.f, l1 = 0.f;

    const __nv_bfloat16* srcs[4] = { kh_g + hb, kl_g + hb, vh_g + hb, vl_g + hb };

#define AISSUE(kt, sbase)                                                        \
    {                                                                            \
        const int kb_ = (kt) * 64;                                               \
        _Pragma("unroll")                                                        \
        for (int t = 0; t < 8; ++t) {                                            \
            const int c = tid + t * 256;                                         \
            const int arr = c >> 9;                                              \
            const int row = (c >> 3) & 63;                                       \
            const int ch = c & 7;                                                \
            const uint32_t dst = sb + (sbase) + arr * 8192 + row * 128           \
                                 + ((ch ^ (row & 7)) << 4);                      \
            cpa16(dst, srcs[arr] + (size_t)(kb_ + row) * DH + ch * 8);           \
        }                                                                        \
    }

    AISSUE(0, 0);
    asm volatile("cp.async.commit_group;" ::: "memory");
    AISSUE(1, ATT_STG);
    asm volatile("cp.async.commit_group;" ::: "memory");

    int stq = 0, stw = 2;
    for (int it = 0; it < nkt; ++it) {
        asm volatile("cp.async.wait_group 1;" ::: "memory");
        __syncthreads();

        const int kb = it * 64;
        const bool act = (kb <= wr0 + 15);
        const uint32_t st = sb + stq * ATT_STG;
        uint32_t ph[4][4], pl[4][4];

        if (act) {
            float s[8][4] = {};

            const int srow_b = (lane & 7) + ((lane >> 4) << 3);
            const int sch_b = (lane >> 3) & 1;
#pragma unroll
            for (int f = 0; f < 4; ++f) {
#pragma unroll
                for (int ng = 0; ng < 4; ++ng) {
                    const int row = ng * 16 + srow_b;
                    const int ch = f * 2 + sch_b;
                    const uint32_t ad = st + row * 128 + ((ch ^ (row & 7)) << 4);
                    uint32_t kh4[4], kl4[4];
                    ldsm4(kh4, ad);
                    ldsm4(kl4, ad + 8192);
#pragma unroll
                    for (int hf = 0; hf < 2; ++hf) {
                        float* ss = s[ng * 2 + hf];
                        mma16816(ss, qfh[f], kh4[hf * 2], kh4[hf * 2 + 1]);
                        mma16816(ss, qfh[f], kl4[hf * 2], kl4[hf * 2 + 1]);
                        mma16816(ss, qfl[f], kh4[hf * 2], kh4[hf * 2 + 1]);
                    }
                }
            }

            if (kb + 63 > wr0) {
                const int r0g = wr0 + (lane >> 2), r1g = r0g + 8;
#pragma unroll
                for (int n8 = 0; n8 < 8; ++n8) {
                    const int c0 = kb + n8 * 8 + (lane & 3) * 2;
                    if (c0 > r0g)     s[n8][0] = -1e30f;
                    if (c0 + 1 > r0g) s[n8][1] = -1e30f;
                    if (c0 > r1g)     s[n8][2] = -1e30f;
                    if (c0 + 1 > r1g) s[n8][3] = -1e30f;
                }
            }

            float t0 = -1e30f, t1 = -1e30f;
#pragma unroll
            for (int n8 = 0; n8 < 8; ++n8) {
                t0 = fmaxf(t0, fmaxf(s[n8][0], s[n8][1]));
                t1 = fmaxf(t1, fmaxf(s[n8][2], s[n8][3]));
            }
            t0 = fmaxf(t0, __shfl_xor_sync(0xffffffff, t0, 1));
            t0 = fmaxf(t0, __shfl_xor_sync(0xffffffff, t0, 2));
            t1 = fmaxf(t1, __shfl_xor_sync(0xffffffff, t1, 1));
            t1 = fmaxf(t1, __shfl_xor_sync(0xffffffff, t1, 2));

            const float mn0 = fmaxf(m0v, t0), mn1 = fmaxf(m1v, t1);
            const float cr0 = ex2(m0v - mn0), cr1 = ex2(m1v - mn1);
            m0v = mn0; m1v = mn1;
            l0 *= cr0; l1 *= cr1;
#pragma unroll
            for (int n8 = 0; n8 < 8; ++n8) {
                O[n8][0] *= cr0; O[n8][1] *= cr0;
                O[n8][2] *= cr1; O[n8][3] *= cr1;
            }

#pragma unroll
            for (int g = 0; g < 4; ++g) {
#pragma unroll
                for (int hf = 0; hf < 2; ++hf) {
                    const float* ss = s[g * 2 + hf];
                    const float p0 = ex2(ss[0] - m0v);
                    const float p1 = ex2(ss[1] - m0v);
                    const float p2 = ex2(ss[2] - m1v);
                    const float p3 = ex2(ss[3] - m1v);
                    l0 += p0 + p1;
                    l1 += p2 + p3;
                    split2t(p0, p1, ph[g][hf * 2], pl[g][hf * 2]);
                    split2t(p2, p3, ph[g][hf * 2 + 1], pl[g][hf * 2 + 1]);
                }
            }
        }

        // overlap next-stage load issue with PV tensor work
        if (it + 2 < nkt) {
            AISSUE(it + 2, stw * ATT_STG);
        }
        asm volatile("cp.async.commit_group;" ::: "memory");

        if (act) {
            const int vrow_b = (lane & 7) + ((lane >> 3) & 1) * 8;
            const int vch_b = lane >> 4;
#pragma unroll
            for (int g = 0; g < 4; ++g) {
                const int row = g * 16 + vrow_b;
#pragma unroll
                for (int no = 0; no < 4; ++no) {
                    const int ch = no * 2 + vch_b;
                    const uint32_t ad = st + 16384 + row * 128 + ((ch ^ (row & 7)) << 4);
                    uint32_t vh4[4], vl4[4];
                    ldsm4t(vh4, ad);
                    ldsm4t(vl4, ad + 8192);
                    float* o0 = O[no * 2];
                    float* o1 = O[no * 2 + 1];
                    mma16816(o0, ph[g], vh4[0], vh4[1]);
                    mma16816(o0, ph[g], vl4[0], vl4[1]);
                    mma16816(o0, pl[g], vh4[0], vh4[1]);
                    mma16816(o1, ph[g], vh4[2], vh4[3]);
                    mma16816(o1, ph[g], vl4[2], vl4[3]);
                    mma16816(o1, pl[g], vh4[2], vh4[3]);
                }
            }
        }
        stq = stq == 2 ? 0 : stq + 1;
        stw = stw == 2 ? 0 : stw + 1;
    }
#undef AISSUE

    l0 += __shfl_xor_sync(0xffffffff, l0, 1);
    l0 += __shfl_xor_sync(0xffffffff, l0, 2);
    l1 += __shfl_xor_sync(0xffffffff, l1, 1);
    l1 += __shfl_xor_sync(0xffffffff, l1, 2);
    const float inv0 = 1.f / l0, inv1 = 1.f / l1;

    const int r = lane >> 2, c2 = (lane & 3) * 2;
    const size_t ob0 = ((size_t)bb * SS + wr0 + r) * DD + h * DH;
    const size_t ob1 = ((size_t)bb * SS + wr0 + r + 8) * DD + h * DH;
#pragma unroll
    for (int n8 = 0; n8 < 8; ++n8) {
        const int col = n8 * 8 + c2;
        uint32_t hi, lo;
        split2t(O[n8][0] * inv0, O[n8][1] * inv0, hi, lo);
        *(uint32_t*)(oh_g + ob0 + col) = hi;
        *(uint32_t*)(ol_g + ob0 + col) = lo;
        split2t(O[n8][2] * inv1, O[n8][3] * inv1, hi, lo);
        *(uint32_t*)(oh_g + ob1 + col) = hi;
        *(uint32_t*)(ol_g + ob1 + col) = lo;
    }
}

// ---------------------------------------------------------------------------
extern "C" void kernel_launch(void* const* d_in, const int* in_sizes, int n_in,
                              void* d_out, int out_size) {
    const float* queries = (const float*)d_in[0];
    const float* keys    = (const float*)d_in[1];
    const float* values  = (const float*)d_in[2];
    const float* W_Q = (const float*)d_in[3];
    const float* b_Q = (const float*)d_in[4];
    const float* W_K = (const float*)d_in[5];
    const float* b_K = (const float*)d_in[6];
    const float* W_V = (const float*)d_in[7];
    const float* b_V = (const float*)d_in[8];
    const float* W_O = (const float*)d_in[9];
    const float* b_O = (const float*)d_in[10];
    float* out = (float*)d_out;

    __nv_bfloat16 *qh, *ql, *kh, *kl, *vh, *vl;
    cudaGetSymbolAddress((void**)&qh, g_qh); cudaGetSymbolAddress((void**)&ql, g_ql);
    cudaGetSymbolAddress((void**)&kh, g_kh); cudaGetSymbolAddress((void**)&kl, g_kl);
    cudaGetSymbolAddress((void**)&vh, g_vh); cudaGetSymbolAddress((void**)&vl, g_vl);

    __nv_bfloat16 *aqh, *aql, *akh, *akl, *avh, *avl, *ath, *atl;
    __nv_bfloat16 *wqh, *wql, *wkh, *wkl, *wvh, *wvl, *woh, *wol;
    cudaGetSymbolAddress((void**)&aqh, g_aq_h); cudaGetSymbolAddress((void**)&aql, g_aq_l);
    cudaGetSymbolAddress((void**)&akh, g_ak_h); cudaGetSymbolAddress((void**)&akl, g_ak_l);
    cudaGetSymbolAddress((void**)&avh, g_av_h); cudaGetSymbolAddress((void**)&avl, g_av_l);
    cudaGetSymbolAddress((void**)&ath, g_at_h); cudaGetSymbolAddress((void**)&atl, g_at_l);
    cudaGetSymbolAddress((void**)&wqh, g_wq_h); cudaGetSymbolAddress((void**)&wql, g_wq_l);
    cudaGetSymbolAddress((void**)&wkh, g_wk_h); cudaGetSymbolAddress((void**)&wkl, g_wk_l);
    cudaGetSymbolAddress((void**)&wvh, g_wv_h); cudaGetSymbolAddress((void**)&wvl, g_wv_l);
    cudaGetSymbolAddress((void**)&woh, g_wo_h); cudaGetSymbolAddress((void**)&wol, g_wo_l);

    static bool attr_set = false;
    if (!attr_set) {
        cudaFuncSetAttribute(gemm_mma<0>, cudaFuncAttributeMaxDynamicSharedMemorySize, GSM_TOTAL);
        cudaFuncSetAttribute(gemm_mma<1>, cudaFuncAttributeMaxDynamicSharedMemorySize, GSM_TOTAL);
        cudaFuncSetAttribute(attn_mma, cudaFuncAttributeMaxDynamicSharedMemorySize, ATT_SMEM);
        attr_set = true;
    }

    const int nAct4 = MM * DD / 4;
    const int nW4   = DD * DD / 4;

    {
        CvtP cp;
        cp.x[0] = queries; cp.hi[0] = aqh; cp.lo[0] = aql; cp.n4[0] = nAct4;
        cp.x[1] = keys;    cp.hi[1] = akh; cp.lo[1] = akl; cp.n4[1] = nAct4;
        cp.x[2] = values;  cp.hi[2] = avh; cp.lo[2] = avl; cp.n4[2] = nAct4;
        cp.x[3] = W_Q;     cp.hi[3] = wqh; cp.lo[3] = wql; cp.n4[3] = nW4;
        cp.x[4] = W_K;     cp.hi[4] = wkh; cp.lo[4] = wkl; cp.n4[4] = nW4;
        cp.x[5] = W_V;     cp.hi[5] = wvh; cp.lo[5] = wvl; cp.n4[5] = nW4;
        cp.x[6] = W_O;     cp.hi[6] = woh; cp.lo[6] = wol; cp.n4[6] = nW4;
        dim3 g((nAct4 + 255) / 256, 7);
        cvt_split7<<<g, 256>>>(cp);
    }

    const float qscale = 0.125f * 1.4426950408889634f;   // log2(e)/8

    {
        GemmP gp = {};
        gp.Ah[0] = aqh; gp.Al[0] = aql; gp.Bh[0] = wqh; gp.Bl[0] = wql;
        gp.Ah[1] = akh; gp.Al[1] = akl; gp.Bh[1] = wkh; gp.Bl[1] = wkl;
        gp.Ah[2] = avh; gp.Al[2] = avl; gp.Bh[2] = wvh; gp.Bl[2] = wvl;
        gp.bias[0] = b_Q; gp.bias[1] = b_K; gp.bias[2] = b_V;
        gp.Ch[0] = qh; gp.Cl[0] = ql;
        gp.Ch[1] = kh; gp.Cl[1] = kl;
        gp.Ch[2] = vh; gp.Cl[2] = vl;
        gp.scale[0] = qscale; gp.scale[1] = 1.0f; gp.scale[2] = 1.0f;
        gp.C = nullptr;
        dim3 g(MM / 128, DD / 256, 3);   // 32 x 4 x 3 = 384 CTAs
        gemm_mma<0><<<g, 256, GSM_TOTAL>>>(gp);
    }

    dim3 agrid(SS / 128, HH, BB);       // 16 x 16 x 2
    attn_mma<<<agrid, 256, ATT_SMEM>>>(qh, ql, kh, kl, vh, vl, ath, atl);

    {
        GemmP gp = {};
        gp.Ah[0] = ath; gp.Al[0] = atl; gp.Bh[0] = woh; gp.Bl[0] = wol;
        gp.bias[0] = b_O;
        gp.scale[0] = 1.0f;
        gp.C = out;
        dim3 g(MM / 128, DD / 256, 1);   // 32 x 4
        gemm_mma<1><<<g, 256, GSM_TOTAL>>>(gp);
    }
}